// round 5
// baseline (speedup 1.0000x reference)
#include <cuda_runtime.h>
#include <math.h>

// Problem dims (fixed by reference)
#define T   4096      // tokens = B*S
#define D   1024      // hidden
#define F   4096      // ffn
#define E   8         // experts
#define BM  64
#define BN  64
#define BK  16

// Scratch (allocation-free: __device__ globals)
__device__ int   g_counts[E];
__device__ int   g_pairs[E * T];     // packed (token<<1)|slot, grouped per expert
__device__ float g_pw[E * T];        // renormalized routing weight per entry
__device__ float g_h[(size_t)2 * T * F];   // SwiGLU activations per pair (134 MB)

// ---------------------------------------------------------------------------
// Zero output + counters (must run every replay; graph-captured)
// ---------------------------------------------------------------------------
__global__ void zero_kernel(float* __restrict__ out) {
    int idx = blockIdx.x * blockDim.x + threadIdx.x;
    const int total = T * D;
    for (int i = idx; i < total; i += gridDim.x * blockDim.x) out[i] = 0.0f;
    if (idx < E) g_counts[idx] = 0;
}

// ---------------------------------------------------------------------------
// Router: logits = x @ gate_w + gate_b, top-2 (softmax monotonic in logits),
// renormalized weights = exp(l)/(exp(l1)+exp(l2)). Compaction via atomics.
// ---------------------------------------------------------------------------
__global__ void router_kernel(const float* __restrict__ x,
                              const float* __restrict__ gw,
                              const float* __restrict__ gb) {
    int t   = blockIdx.x;
    int tid = threadIdx.x;              // 128 threads
    __shared__ float s[128][E];

    float acc[E];
#pragma unroll
    for (int e = 0; e < E; e++) acc[e] = 0.0f;

    const float* xr = x + (size_t)t * D;
    for (int d = tid; d < D; d += 128) {
        float xv = xr[d];
#pragma unroll
        for (int e = 0; e < E; e++) acc[e] += xv * gw[d * E + e];
    }
#pragma unroll
    for (int e = 0; e < E; e++) s[tid][e] = acc[e];
    __syncthreads();

    if (tid == 0) {
        float l[E];
#pragma unroll
        for (int e = 0; e < E; e++) {
            float a = 0.0f;
            for (int i = 0; i < 128; i++) a += s[i][e];
            l[e] = a + gb[e];
        }
        // top-2, lowest index wins ties (matches jax top_k)
        int i1 = 0;
        for (int e = 1; e < E; e++) if (l[e] > l[i1]) i1 = e;
        int i2 = -1;
        for (int e = 0; e < E; e++) {
            if (e == i1) continue;
            if (i2 < 0 || l[e] > l[i2]) i2 = e;
        }
        // renorm: softmax denominator cancels
        float wb  = expf(l[i2] - l[i1]);     // <= 1, stable
        float w1n = 1.0f / (1.0f + wb);
        float w2n = wb * w1n;

        int p0 = atomicAdd(&g_counts[i1], 1);
        g_pairs[i1 * T + p0] = (t << 1);
        g_pw[i1 * T + p0]    = w1n;
        int p1 = atomicAdd(&g_counts[i2], 1);
        g_pairs[i2 * T + p1] = (t << 1) | 1;
        g_pw[i2 * T + p1]    = w2n;
    }
}

// ---------------------------------------------------------------------------
// GEMM1: per expert, H[pair, f] = silu(x @ w1) * (x @ w3).
// M = tokens routed to expert (gathered), N = F, K = D.
// Dual accumulators, SwiGLU fused in epilogue.
// ---------------------------------------------------------------------------
__global__ void gemm1_kernel(const float* __restrict__ x,
                             const float* __restrict__ w1,
                             const float* __restrict__ w3) {
    int e   = blockIdx.z;
    int cnt = g_counts[e];
    int m0  = blockIdx.y * BM;
    if (m0 >= cnt) return;
    int n0  = blockIdx.x * BN;

    __shared__ float As[BK][BM];
    __shared__ float B1s[BK][BN];
    __shared__ float B3s[BK][BN];

    int tid = threadIdx.x;              // 256
    int tx = tid & 15, ty = tid >> 4;

    // A-load assignment: one float4 of one gathered row per thread
    int arow = tid >> 2;                // 0..63
    int akq  = (tid & 3) * 4;           // 0,4,8,12
    int am   = m0 + arow;
    const float* xrow = nullptr;
    if (am < cnt) {
        int pair = g_pairs[e * T + am];
        xrow = x + (size_t)(pair >> 1) * D;
    }
    // B-load assignment
    int brow = tid >> 4;                // 0..15
    int bfq  = (tid & 15) * 4;          // 0..60
    const float* w1p = w1 + (size_t)e * D * F;
    const float* w3p = w3 + (size_t)e * D * F;

    float acc1[16], acc3[16];
#pragma unroll
    for (int i = 0; i < 16; i++) { acc1[i] = 0.0f; acc3[i] = 0.0f; }

    for (int k0 = 0; k0 < D; k0 += BK) {
        float4 av = make_float4(0.f, 0.f, 0.f, 0.f);
        if (xrow) av = *(const float4*)(xrow + k0 + akq);
        As[akq + 0][arow] = av.x;
        As[akq + 1][arow] = av.y;
        As[akq + 2][arow] = av.z;
        As[akq + 3][arow] = av.w;

        *(float4*)&B1s[brow][bfq] =
            *(const float4*)(w1p + (size_t)(k0 + brow) * F + n0 + bfq);
        *(float4*)&B3s[brow][bfq] =
            *(const float4*)(w3p + (size_t)(k0 + brow) * F + n0 + bfq);
        __syncthreads();

#pragma unroll
        for (int k = 0; k < BK; k++) {
            float4 a  = *(const float4*)&As[k][ty * 4];
            float4 b1 = *(const float4*)&B1s[k][tx * 4];
            float4 b3 = *(const float4*)&B3s[k][tx * 4];
            float av_[4] = {a.x, a.y, a.z, a.w};
            float b1_[4] = {b1.x, b1.y, b1.z, b1.w};
            float b3_[4] = {b3.x, b3.y, b3.z, b3.w};
#pragma unroll
            for (int i = 0; i < 4; i++)
#pragma unroll
                for (int j = 0; j < 4; j++) {
                    acc1[i * 4 + j] += av_[i] * b1_[j];
                    acc3[i * 4 + j] += av_[i] * b3_[j];
                }
        }
        __syncthreads();
    }

#pragma unroll
    for (int i = 0; i < 4; i++) {
        int m = m0 + ty * 4 + i;
        if (m >= cnt) continue;
        int pair = g_pairs[e * T + m];
        float* hrow = g_h + (size_t)pair * F + n0 + tx * 4;
        float4 hv;
        float* hp = &hv.x;
#pragma unroll
        for (int j = 0; j < 4; j++) {
            float v1  = acc1[i * 4 + j];
            float v3  = acc3[i * 4 + j];
            float sig = 1.0f / (1.0f + expf(-v1));
            hp[j] = v1 * sig * v3;
        }
        *(float4*)hrow = hv;
    }
}

// ---------------------------------------------------------------------------
// GEMM2: per expert, out[t] += w * (H[pair] @ w2).  M = routed tokens,
// N = D, K = F. Weighted atomicAdd combine (commutative -> deterministic).
// ---------------------------------------------------------------------------
__global__ void gemm2_kernel(const float* __restrict__ w2,
                             float* __restrict__ out) {
    int e   = blockIdx.z;
    int cnt = g_counts[e];
    int m0  = blockIdx.y * BM;
    if (m0 >= cnt) return;
    int n0  = blockIdx.x * BN;

    __shared__ float As[BK][BM];
    __shared__ float Bs[BK][BN];

    int tid = threadIdx.x;
    int tx = tid & 15, ty = tid >> 4;

    int arow = tid >> 2;
    int akq  = (tid & 3) * 4;
    int am   = m0 + arow;
    const float* hrow = nullptr;
    if (am < cnt) hrow = g_h + (size_t)g_pairs[e * T + am] * F;

    int brow = tid >> 4;
    int bfq  = (tid & 15) * 4;
    const float* w2p = w2 + (size_t)e * F * D;

    float acc[16];
#pragma unroll
    for (int i = 0; i < 16; i++) acc[i] = 0.0f;

    for (int k0 = 0; k0 < F; k0 += BK) {
        float4 av = make_float4(0.f, 0.f, 0.f, 0.f);
        if (hrow) av = *(const float4*)(hrow + k0 + akq);
        As[akq + 0][arow] = av.x;
        As[akq + 1][arow] = av.y;
        As[akq + 2][arow] = av.z;
        As[akq + 3][arow] = av.w;

        *(float4*)&Bs[brow][bfq] =
            *(const float4*)(w2p + (size_t)(k0 + brow) * D + n0 + bfq);
        __syncthreads();

#pragma unroll
        for (int k = 0; k < BK; k++) {
            float4 a = *(const float4*)&As[k][ty * 4];
            float4 b = *(const float4*)&Bs[k][tx * 4];
            float av_[4] = {a.x, a.y, a.z, a.w};
            float bv_[4] = {b.x, b.y, b.z, b.w};
#pragma unroll
            for (int i = 0; i < 4; i++)
#pragma unroll
                for (int j = 0; j < 4; j++)
                    acc[i * 4 + j] += av_[i] * bv_[j];
        }
        __syncthreads();
    }

#pragma unroll
    for (int i = 0; i < 4; i++) {
        int m = m0 + ty * 4 + i;
        if (m >= cnt) continue;
        int pair = g_pairs[e * T + m];
        int t    = pair >> 1;
        float w  = g_pw[e * T + m];
        float* orow = out + (size_t)t * D + n0 + tx * 4;
#pragma unroll
        for (int j = 0; j < 4; j++)
            atomicAdd(&orow[j], w * acc[i * 4 + j]);
    }
}

// ---------------------------------------------------------------------------
extern "C" void kernel_launch(void* const* d_in, const int* in_sizes, int n_in,
                              void* d_out, int out_size) {
    const float* x  = (const float*)d_in[0];   // [T, D]
    const float* gw = (const float*)d_in[1];   // [D, E]
    const float* gb = (const float*)d_in[2];   // [E]
    const float* w1 = (const float*)d_in[3];   // [E, D, F]
    const float* w3 = (const float*)d_in[4];   // [E, D, F]
    const float* w2 = (const float*)d_in[5];   // [E, F, D]
    float* out = (float*)d_out;                // [T, D]

    zero_kernel<<<2048, 256>>>(out);
    router_kernel<<<T, 128>>>(x, gw, gb);
    gemm1_kernel<<<dim3(F / BN, T / BM, E), 256>>>(x, w1, w3);
    gemm2_kernel<<<dim3(D / BN, T / BM, E), 256>>>(w2, out);
}

// round 8
// speedup vs baseline: 1.1653x; 1.1653x over previous
#include <cuda_runtime.h>
#include <math.h>
#include <stdint.h>

// Problem dims (fixed by reference)
#define T   4096      // tokens = B*S
#define D   1024      // hidden
#define F   4096      // ffn
#define E   8         // experts
#define ASTR 36       // smem row stride (floats): 32 + 4 pad -> conflict-free frags

// ---------------------------------------------------------------------------
// Scratch (allocation-free: __device__ globals)
// ---------------------------------------------------------------------------
__device__ int   g_counts[E];
__device__ int   g_pairs[E * T];     // packed (token<<1)|slot, grouped per expert
__device__ float g_pw[E * T];        // renormalized routing weight per entry
__device__ float g_h[(size_t)2 * T * F];   // SwiGLU activations per pair

// ---------------------------------------------------------------------------
// tf32 helpers (sm_80+ ISA only — NO sm_103a-gated instructions)
// ---------------------------------------------------------------------------
__device__ __forceinline__ uint32_t f2tf(float f) {
    uint32_t r;
    asm("cvt.rna.tf32.f32 %0, %1;" : "=r"(r) : "f"(f));
    return r;
}

// D(16x8) += A(16x8,row) * B(8x8,col)  tf32 in, fp32 accum
__device__ __forceinline__ void mma8(float* c, const uint32_t* a, const uint32_t* b) {
    asm volatile(
        "mma.sync.aligned.m16n8k8.row.col.f32.tf32.tf32.f32 "
        "{%0,%1,%2,%3}, {%4,%5,%6,%7}, {%8,%9}, {%0,%1,%2,%3};"
        : "+f"(c[0]), "+f"(c[1]), "+f"(c[2]), "+f"(c[3])
        : "r"(a[0]), "r"(a[1]), "r"(a[2]), "r"(a[3]), "r"(b[0]), "r"(b[1]));
}

// ---------------------------------------------------------------------------
// Zero output + counters
// ---------------------------------------------------------------------------
__global__ void zero_kernel(float* __restrict__ out) {
    int idx = blockIdx.x * blockDim.x + threadIdx.x;
    const int total = T * D;
    for (int i = idx; i < total; i += gridDim.x * blockDim.x) out[i] = 0.0f;
    if (idx < E) g_counts[idx] = 0;
}

// ---------------------------------------------------------------------------
// Router (unchanged — known correct)
// ---------------------------------------------------------------------------
__global__ void router_kernel(const float* __restrict__ x,
                              const float* __restrict__ gw,
                              const float* __restrict__ gb) {
    int t   = blockIdx.x;
    int tid = threadIdx.x;              // 128 threads
    __shared__ float s[128][E];

    float acc[E];
#pragma unroll
    for (int e = 0; e < E; e++) acc[e] = 0.0f;

    const float* xr = x + (size_t)t * D;
    for (int d = tid; d < D; d += 128) {
        float xv = xr[d];
#pragma unroll
        for (int e = 0; e < E; e++) acc[e] += xv * gw[d * E + e];
    }
#pragma unroll
    for (int e = 0; e < E; e++) s[tid][e] = acc[e];
    __syncthreads();

    if (tid == 0) {
        float l[E];
#pragma unroll
        for (int e = 0; e < E; e++) {
            float a = 0.0f;
            for (int i = 0; i < 128; i++) a += s[i][e];
            l[e] = a + gb[e];
        }
        int i1 = 0;
        for (int e = 1; e < E; e++) if (l[e] > l[i1]) i1 = e;
        int i2 = -1;
        for (int e = 0; e < E; e++) {
            if (e == i1) continue;
            if (i2 < 0 || l[e] > l[i2]) i2 = e;
        }
        float wb  = expf(l[i2] - l[i1]);
        float w1n = 1.0f / (1.0f + wb);
        float w2n = wb * w1n;

        int p0 = atomicAdd(&g_counts[i1], 1);
        g_pairs[i1 * T + p0] = (t << 1);
        g_pw[i1 * T + p0]    = w1n;
        int p1 = atomicAdd(&g_counts[i2], 1);
        g_pairs[i2 * T + p1] = (t << 1) | 1;
        g_pw[i2 * T + p1]    = w2n;
    }
}

// ---------------------------------------------------------------------------
// GEMM1 (tf32 mma.sync): tile 128(M gathered) x 64(F), K=D in 32-chunks.
// Dual accumulators (x@w1, x@w3); SwiGLU fused in epilogue -> g_h.
// SMEM per buffer: A 128x36 + B1 64x36 + B3 64x36 = 9216 floats; x2 buffers.
// ---------------------------------------------------------------------------
#define G1_BUF  9216
#define G1_SMEM (2 * G1_BUF * 4)
#define G2_BUF  9216
#define G2_SMEM (2 * G2_BUF * 4)

__global__ __launch_bounds__(256, 1)
void gemm1_mma(const float* __restrict__ x,
               const float* __restrict__ w1,
               const float* __restrict__ w3) {
    int e   = blockIdx.z;
    int cnt = g_counts[e];
    int m0  = blockIdx.x * 128;
    if (m0 >= cnt) return;
    int n0  = blockIdx.y * 64;

    extern __shared__ uint32_t sm[];
    int tid = threadIdx.x;

    // --- staging assignments ---
    // A: 128 rows x 32 k floats; 2 threads/row, each 4 float4 (half-row)
    int arow = tid >> 1, ah = tid & 1;
    const float* asrc = nullptr;
    if (m0 + arow < cnt)
        asrc = x + (size_t)(g_pairs[e * T + m0 + arow] >> 1) * D + ah * 16;
    // B: threads [0,128) stage w1, [128,256) stage w3; 32k x 64n each
    int bt = tid & 127;
    int bk = bt & 7;                 // k within chunk-of-8
    int bn = (bt >> 3) * 4;          // n (float4 granule)
    const float* bsrc = ((tid < 128) ? w1 : w3) + (size_t)e * D * F + n0 + bn;
    int bso = (tid < 128) ? 4608 : 6912;   // region offset within buffer (floats)

    // --- fragment assignments: 8 warps = 4(M) x 2(N), warp tile 32x32 ---
    int wid = tid >> 5, lane = tid & 31;
    int wm = (wid >> 1) * 32, wn = (wid & 1) * 32;
    int r = lane >> 2, c = lane & 3;

    float acc1[2][4][4], acc3[2][4][4];
#pragma unroll
    for (int mi = 0; mi < 2; mi++)
#pragma unroll
        for (int nj = 0; nj < 4; nj++)
#pragma unroll
            for (int q = 0; q < 4; q++) { acc1[mi][nj][q] = 0.f; acc3[mi][nj][q] = 0.f; }

    const int KT = D / 32;           // 32

    float4 Ar[4], Br[4];
    // stage tile 0
#pragma unroll
    for (int i = 0; i < 4; i++) {
        Ar[i] = asrc ? *(const float4*)(asrc + i * 4) : make_float4(0.f, 0.f, 0.f, 0.f);
        Br[i] = *(const float4*)(bsrc + (size_t)(bk + 8 * i) * F);
    }
    {   // store to buffer 0 (tf32-converted)
        uint32_t* dA = sm;
        uint32_t* dB = sm + bso;
#pragma unroll
        for (int i = 0; i < 4; i++) {
            uint32_t* p = dA + arow * ASTR + ah * 16 + i * 4;
            p[0] = f2tf(Ar[i].x); p[1] = f2tf(Ar[i].y);
            p[2] = f2tf(Ar[i].z); p[3] = f2tf(Ar[i].w);
            const float* bv = &Br[i].x;
#pragma unroll
            for (int j = 0; j < 4; j++)
                dB[(bn + j) * ASTR + bk + 8 * i] = f2tf(bv[j]);
        }
    }
    __syncthreads();

    for (int kt = 0; kt < KT; kt++) {
        int buf = kt & 1;
        if (kt + 1 < KT) {           // prefetch next tile into regs
#pragma unroll
            for (int i = 0; i < 4; i++) {
                Ar[i] = asrc ? *(const float4*)(asrc + (kt + 1) * 32 + i * 4)
                             : make_float4(0.f, 0.f, 0.f, 0.f);
                Br[i] = *(const float4*)(bsrc + (size_t)((kt + 1) * 32 + bk + 8 * i) * F);
            }
        }
        // compute on current buffer
        const uint32_t* A  = sm + buf * G1_BUF;
        const uint32_t* B1 = A + 4608;
        const uint32_t* B3 = A + 6912;
#pragma unroll
        for (int ks = 0; ks < 4; ks++) {
            int kc = ks * 8 + c;
            uint32_t af[2][4];
#pragma unroll
            for (int mi = 0; mi < 2; mi++) {
                int row = wm + mi * 16 + r;
                af[mi][0] = A[row * ASTR + kc];
                af[mi][1] = A[(row + 8) * ASTR + kc];
                af[mi][2] = A[row * ASTR + kc + 4];
                af[mi][3] = A[(row + 8) * ASTR + kc + 4];
            }
            uint32_t bf1[4][2], bf3[4][2];
#pragma unroll
            for (int nj = 0; nj < 4; nj++) {
                int n = wn + nj * 8 + r;
                bf1[nj][0] = B1[n * ASTR + kc];
                bf1[nj][1] = B1[n * ASTR + kc + 4];
                bf3[nj][0] = B3[n * ASTR + kc];
                bf3[nj][1] = B3[n * ASTR + kc + 4];
            }
#pragma unroll
            for (int mi = 0; mi < 2; mi++)
#pragma unroll
                for (int nj = 0; nj < 4; nj++) {
                    mma8(acc1[mi][nj], af[mi], bf1[nj]);
                    mma8(acc3[mi][nj], af[mi], bf3[nj]);
                }
        }
        if (kt + 1 < KT) {
            __syncthreads();         // everyone done reading buf^1 (used at kt-1)
            uint32_t* dA = sm + (buf ^ 1) * G1_BUF;
            uint32_t* dB = dA + bso;
#pragma unroll
            for (int i = 0; i < 4; i++) {
                uint32_t* p = dA + arow * ASTR + ah * 16 + i * 4;
                p[0] = f2tf(Ar[i].x); p[1] = f2tf(Ar[i].y);
                p[2] = f2tf(Ar[i].z); p[3] = f2tf(Ar[i].w);
                const float* bv = &Br[i].x;
#pragma unroll
                for (int j = 0; j < 4; j++)
                    dB[(bn + j) * ASTR + bk + 8 * i] = f2tf(bv[j]);
            }
            __syncthreads();
        }
    }

    // Epilogue: SwiGLU, write g_h
#pragma unroll
    for (int mi = 0; mi < 2; mi++)
#pragma unroll
        for (int h = 0; h < 2; h++) {
            int m = m0 + wm + mi * 16 + r + h * 8;
            if (m >= cnt) continue;
            float* hrow = g_h + (size_t)g_pairs[e * T + m] * F + n0;
#pragma unroll
            for (int nj = 0; nj < 4; nj++) {
                float a0 = acc1[mi][nj][h * 2],     a1 = acc1[mi][nj][h * 2 + 1];
                float b0 = acc3[mi][nj][h * 2],     b1 = acc3[mi][nj][h * 2 + 1];
                float2 v;
                v.x = a0 / (1.0f + __expf(-a0)) * b0;
                v.y = a1 / (1.0f + __expf(-a1)) * b1;
                *(float2*)(hrow + wn + nj * 8 + c * 2) = v;
            }
        }
}

// ---------------------------------------------------------------------------
// GEMM2 (tf32 mma.sync): tile 128(M gathered) x 128(D), K=F in 32-chunks.
// Weighted atomicAdd combine epilogue.
// SMEM per buffer: A 128x36 + B 128x36 = 9216 floats; x2 buffers.
// ---------------------------------------------------------------------------
__global__ __launch_bounds__(256, 1)
void gemm2_mma(const float* __restrict__ w2, float* __restrict__ out) {
    int e   = blockIdx.z;
    int cnt = g_counts[e];
    int m0  = blockIdx.x * 128;
    if (m0 >= cnt) return;
    int n0  = blockIdx.y * 128;

    extern __shared__ uint32_t sm[];
    int tid = threadIdx.x;

    // A staging: from g_h gathered rows
    int arow = tid >> 1, ah = tid & 1;
    const float* asrc = nullptr;
    if (m0 + arow < cnt)
        asrc = g_h + (size_t)g_pairs[e * T + m0 + arow] * F + ah * 16;
    // B staging: w2 [F][D], 32k x 128n; all 256 threads
    int bk = tid & 7;
    int bn = (tid >> 3) * 4;         // 0..124
    const float* bsrc = w2 + (size_t)e * F * D + n0 + bn;

    // fragments: 8 warps = 2(M) x 4(N), warp tile 64x32
    int wid = tid >> 5, lane = tid & 31;
    int wm = (wid >> 2) * 64, wn = (wid & 3) * 32;
    int r = lane >> 2, c = lane & 3;

    float acc[4][4][4];
#pragma unroll
    for (int mi = 0; mi < 4; mi++)
#pragma unroll
        for (int nj = 0; nj < 4; nj++)
#pragma unroll
            for (int q = 0; q < 4; q++) acc[mi][nj][q] = 0.f;

    const int KT = F / 32;           // 128

    float4 Ar[4], Br[4];
#pragma unroll
    for (int i = 0; i < 4; i++) {
        Ar[i] = asrc ? *(const float4*)(asrc + i * 4) : make_float4(0.f, 0.f, 0.f, 0.f);
        Br[i] = *(const float4*)(bsrc + (size_t)(bk + 8 * i) * D);
    }
    {
        uint32_t* dA = sm;
        uint32_t* dB = sm + 4608;
#pragma unroll
        for (int i = 0; i < 4; i++) {
            uint32_t* p = dA + arow * ASTR + ah * 16 + i * 4;
            p[0] = f2tf(Ar[i].x); p[1] = f2tf(Ar[i].y);
            p[2] = f2tf(Ar[i].z); p[3] = f2tf(Ar[i].w);
            const float* bv = &Br[i].x;
#pragma unroll
            for (int j = 0; j < 4; j++)
                dB[(bn + j) * ASTR + bk + 8 * i] = f2tf(bv[j]);
        }
    }
    __syncthreads();

    for (int kt = 0; kt < KT; kt++) {
        int buf = kt & 1;
        if (kt + 1 < KT) {
#pragma unroll
            for (int i = 0; i < 4; i++) {
                Ar[i] = asrc ? *(const float4*)(asrc + (kt + 1) * 32 + i * 4)
                             : make_float4(0.f, 0.f, 0.f, 0.f);
                Br[i] = *(const float4*)(bsrc + (size_t)((kt + 1) * 32 + bk + 8 * i) * D);
            }
        }
        const uint32_t* A = sm + buf * G2_BUF;
        const uint32_t* B = A + 4608;
#pragma unroll
        for (int ks = 0; ks < 4; ks++) {
            int kc = ks * 8 + c;
            uint32_t af[4][4];
#pragma unroll
            for (int mi = 0; mi < 4; mi++) {
                int row = wm + mi * 16 + r;
                af[mi][0] = A[row * ASTR + kc];
                af[mi][1] = A[(row + 8) * ASTR + kc];
                af[mi][2] = A[row * ASTR + kc + 4];
                af[mi][3] = A[(row + 8) * ASTR + kc + 4];
            }
            uint32_t bf[4][2];
#pragma unroll
            for (int nj = 0; nj < 4; nj++) {
                int n = wn + nj * 8 + r;
                bf[nj][0] = B[n * ASTR + kc];
                bf[nj][1] = B[n * ASTR + kc + 4];
            }
#pragma unroll
            for (int mi = 0; mi < 4; mi++)
#pragma unroll
                for (int nj = 0; nj < 4; nj++)
                    mma8(acc[mi][nj], af[mi], bf[nj]);
        }
        if (kt + 1 < KT) {
            __syncthreads();
            uint32_t* dA = sm + (buf ^ 1) * G2_BUF;
            uint32_t* dB = dA + 4608;
#pragma unroll
            for (int i = 0; i < 4; i++) {
                uint32_t* p = dA + arow * ASTR + ah * 16 + i * 4;
                p[0] = f2tf(Ar[i].x); p[1] = f2tf(Ar[i].y);
                p[2] = f2tf(Ar[i].z); p[3] = f2tf(Ar[i].w);
                const float* bv = &Br[i].x;
#pragma unroll
                for (int j = 0; j < 4; j++)
                    dB[(bn + j) * ASTR + bk + 8 * i] = f2tf(bv[j]);
            }
            __syncthreads();
        }
    }

    // Epilogue: weighted combine via atomicAdd (commutative -> deterministic)
#pragma unroll
    for (int mi = 0; mi < 4; mi++)
#pragma unroll
        for (int h = 0; h < 2; h++) {
            int m = m0 + wm + mi * 16 + r + h * 8;
            if (m >= cnt) continue;
            int pair = g_pairs[e * T + m];
            float w  = g_pw[e * T + m];
            float* orow = out + (size_t)(pair >> 1) * D + n0;
#pragma unroll
            for (int nj = 0; nj < 4; nj++) {
                int col = wn + nj * 8 + c * 2;
                atomicAdd(orow + col,     w * acc[mi][nj][h * 2]);
                atomicAdd(orow + col + 1, w * acc[mi][nj][h * 2 + 1]);
            }
        }
}

// ---------------------------------------------------------------------------
extern "C" void kernel_launch(void* const* d_in, const int* in_sizes, int n_in,
                              void* d_out, int out_size) {
    const float* x  = (const float*)d_in[0];   // [T, D]
    const float* gw = (const float*)d_in[1];   // [D, E]
    const float* gb = (const float*)d_in[2];   // [E]
    const float* w1 = (const float*)d_in[3];   // [E, D, F]
    const float* w3 = (const float*)d_in[4];   // [E, D, F]
    const float* w2 = (const float*)d_in[5];   // [E, F, D]
    float* out = (float*)d_out;                // [T, D]

    (void)cudaFuncSetAttribute(gemm1_mma, cudaFuncAttributeMaxDynamicSharedMemorySize, G1_SMEM);
    (void)cudaFuncSetAttribute(gemm2_mma, cudaFuncAttributeMaxDynamicSharedMemorySize, G2_SMEM);

    zero_kernel<<<2048, 256>>>(out);
    router_kernel<<<T, 128>>>(x, gw, gb);
    gemm1_mma<<<dim3(T / 128, F / 64, E), 256, G1_SMEM>>>(x, w1, w3);
    gemm2_mma<<<dim3(T / 128, D / 128, E), 256, G2_SMEM>>>(w2, out);
}

// round 12
// speedup vs baseline: 1.2378x; 1.0622x over previous
#include <cuda_runtime.h>
#include <math.h>
#include <stdint.h>

// Problem dims (fixed by reference)
#define T   4096      // tokens = B*S
#define D   1024      // hidden
#define F   4096      // ffn
#define E   8         // experts

// ---------------------------------------------------------------------------
// Scratch (allocation-free: __device__ globals)
// ---------------------------------------------------------------------------
__device__ int   g_counts[E];
__device__ int   g_pairs[E * T];     // packed (token<<1)|slot, grouped per expert
__device__ float g_pw[E * T];        // renormalized routing weight per entry
__device__ float g_h[(size_t)2 * T * F];   // SwiGLU activations per pair

// ---------------------------------------------------------------------------
// tf32 helpers (sm_80+ ISA only)
// ---------------------------------------------------------------------------
__device__ __forceinline__ uint32_t f2tf(float f) {
    uint32_t r;
    asm("cvt.rna.tf32.f32 %0, %1;" : "=r"(r) : "f"(f));
    return r;
}

__device__ __forceinline__ void mma8(float* c, const uint32_t* a, const uint32_t* b) {
    asm volatile(
        "mma.sync.aligned.m16n8k8.row.col.f32.tf32.tf32.f32 "
        "{%0,%1,%2,%3}, {%4,%5,%6,%7}, {%8,%9}, {%0,%1,%2,%3};"
        : "+f"(c[0]), "+f"(c[1]), "+f"(c[2]), "+f"(c[3])
        : "r"(a[0]), "r"(a[1]), "r"(a[2]), "r"(a[3]), "r"(b[0]), "r"(b[1]));
}

// ---------------------------------------------------------------------------
// Zero output + counters
// ---------------------------------------------------------------------------
__global__ void zero_kernel(float* __restrict__ out) {
    int idx = blockIdx.x * blockDim.x + threadIdx.x;
    const int total = T * D;
    for (int i = idx; i < total; i += gridDim.x * blockDim.x) out[i] = 0.0f;
    if (idx < E) g_counts[idx] = 0;
}

// ---------------------------------------------------------------------------
// Router (unchanged — known correct)
// ---------------------------------------------------------------------------
__global__ void router_kernel(const float* __restrict__ x,
                              const float* __restrict__ gw,
                              const float* __restrict__ gb) {
    int t   = blockIdx.x;
    int tid = threadIdx.x;              // 128 threads
    __shared__ float s[128][E];

    float acc[E];
#pragma unroll
    for (int e = 0; e < E; e++) acc[e] = 0.0f;

    const float* xr = x + (size_t)t * D;
    for (int d = tid; d < D; d += 128) {
        float xv = xr[d];
#pragma unroll
        for (int e = 0; e < E; e++) acc[e] += xv * gw[d * E + e];
    }
#pragma unroll
    for (int e = 0; e < E; e++) s[tid][e] = acc[e];
    __syncthreads();

    if (tid == 0) {
        float l[E];
#pragma unroll
        for (int e = 0; e < E; e++) {
            float a = 0.0f;
            for (int i = 0; i < 128; i++) a += s[i][e];
            l[e] = a + gb[e];
        }
        int i1 = 0;
        for (int e = 1; e < E; e++) if (l[e] > l[i1]) i1 = e;
        int i2 = -1;
        for (int e = 0; e < E; e++) {
            if (e == i1) continue;
            if (i2 < 0 || l[e] > l[i2]) i2 = e;
        }
        float wb  = expf(l[i2] - l[i1]);
        float w1n = 1.0f / (1.0f + wb);
        float w2n = wb * w1n;

        int p0 = atomicAdd(&g_counts[i1], 1);
        g_pairs[i1 * T + p0] = (t << 1);
        g_pw[i1 * T + p0]    = w1n;
        int p1 = atomicAdd(&g_counts[i2], 1);
        g_pairs[i2 * T + p1] = (t << 1) | 1;
        g_pw[i2 * T + p1]    = w2n;
    }
}

// ===========================================================================
// Fragment-major SMEM layouts (per 32-wide K tile):
//  A tile (Mt rows x 32 k): frag (mt = row/16, kc = k/8); lane l=(row&7)*4+(k&3)
//    holds 4 regs j = ((row>>3)&1) + 2*((k>>2)&1)
//    addr = ((mt*4+kc)*32 + l)*4 + j            -> compute: one LDS.128 / frag
//  B tile (Nt cols x 32 k): frag (nt = n/8, kc); lane l=(n&7)*4+(k&3),
//    2 regs j = (k>>2)&1
//    addr = ((nt*4+kc)*32 + l)*2 + j            -> compute: one LDS.64 / frag
// ===========================================================================

#define G1_SMEM 65536     // 2 buffers x 8192 uint32 (A 4096 + B1 2048 + B3 2048)
#define G2_SMEM 65536     // 2 buffers x 8192 uint32 (A 4096 + B 4096)

// ---------------------------------------------------------------------------
// GEMM1: tile 128(M gathered) x 64(F), K=D (32 k-tiles of 32).
// 16 warps: warps 0-7 compute X@W1, warps 8-15 compute X@W3 (same m,n block),
// each group = 4Mx2N warp grid, warp tile 32x32. SwiGLU via SMEM exchange,
// coalesced float4 writes to g_h.
// ---------------------------------------------------------------------------
__global__ __launch_bounds__(512, 1)
void gemm1_mma(const float* __restrict__ x,
               const float* __restrict__ w1,
               const float* __restrict__ w3) {
    int e   = blockIdx.z;
    int cnt = g_counts[e];
    int m0  = blockIdx.x * 128;
    if (m0 >= cnt) return;
    int n0  = blockIdx.y * 64;

    extern __shared__ uint32_t sm[];
    int tid = threadIdx.x;

    // ---- A staging: 4 threads/row, each 2 float4 (8 k) ----
    int arow = tid >> 2, aq = tid & 3;
    const float* asrc = (m0 + arow < cnt)
        ? x + (size_t)(g_pairs[e * T + m0 + arow] >> 1) * D + aq * 8 : nullptr;
    int a_s0 = (((arow >> 4) * 4 + aq) * 32 + (arow & 7) * 4) * 4 + ((arow >> 3) & 1);

    // ---- B staging: threads 0-255 -> w1, 256-511 -> w3; 2 float4 each ----
    int bgrp = tid >> 8;
    int bt   = tid & 255;
    int bk   = bt >> 3;                  // 0..31
    int bnq  = (bt & 7) * 2;             // even, 0..14
    const float* bmat = (bgrp ? w3 : w1) + (size_t)e * D * F + n0 + bnq * 4;
    int b_s0 = (4096 + bgrp * 2048)
             + (((bnq >> 1) * 4 + (bk >> 3)) * 32 + (bk & 3)) * 2 + ((bk >> 2) & 1);
    // second nq (bnq+1): +16 on lane -> +32 floats

    // ---- compute mapping ----
    int wid = tid >> 5, lane = tid & 31;
    int grp = wid >> 3;                  // 0: w1, 1: w3
    int gw  = wid & 7;
    int wm  = (gw >> 1) * 32, wn = (gw & 1) * 32;
    int r = lane >> 2, c = lane & 3;
    int mtb = wm >> 4;                   // mt base
    int ntb = wn >> 3;                   // nt base
    int bregion = 4096 + grp * 2048;

    float acc[2][4][4];
#pragma unroll
    for (int mi = 0; mi < 2; mi++)
#pragma unroll
        for (int nj = 0; nj < 4; nj++)
#pragma unroll
            for (int q = 0; q < 4; q++) acc[mi][nj][q] = 0.f;

    const int KT = D / 32;               // 32

    float4 Av0, Av1, Bv0, Bv1;
    // stage tile 0
    Av0 = asrc ? *(const float4*)(asrc)     : make_float4(0.f, 0.f, 0.f, 0.f);
    Av1 = asrc ? *(const float4*)(asrc + 4) : make_float4(0.f, 0.f, 0.f, 0.f);
    Bv0 = *(const float4*)(bmat + (size_t)bk * F);
    Bv1 = *(const float4*)(bmat + (size_t)bk * F + 4);
    {
        uint32_t* d = sm;
        const float* a0 = &Av0.x; const float* a1 = &Av1.x;
#pragma unroll
        for (int j = 0; j < 4; j++) {
            d[a_s0 + j * 4]     = f2tf(a0[j]);
            d[a_s0 + j * 4 + 2] = f2tf(a1[j]);
        }
        const float* b0 = &Bv0.x; const float* b1 = &Bv1.x;
#pragma unroll
        for (int j = 0; j < 4; j++) {
            d[b_s0 + j * 8]      = f2tf(b0[j]);
            d[b_s0 + 32 + j * 8] = f2tf(b1[j]);
        }
    }
    __syncthreads();

    for (int kt = 0; kt < KT; kt++) {
        int buf = kt & 1;
        if (kt + 1 < KT) {
            Av0 = asrc ? *(const float4*)(asrc + (kt + 1) * 32)     : make_float4(0.f, 0.f, 0.f, 0.f);
            Av1 = asrc ? *(const float4*)(asrc + (kt + 1) * 32 + 4) : make_float4(0.f, 0.f, 0.f, 0.f);
            Bv0 = *(const float4*)(bmat + (size_t)((kt + 1) * 32 + bk) * F);
            Bv1 = *(const float4*)(bmat + (size_t)((kt + 1) * 32 + bk) * F + 4);
        }
        const uint32_t* A = sm + buf * 8192;
        const uint32_t* B = sm + buf * 8192 + bregion;
#pragma unroll
        for (int ks = 0; ks < 4; ks++) {
            uint4 af[2];
#pragma unroll
            for (int mi = 0; mi < 2; mi++)
                af[mi] = *(const uint4*)(A + (((mtb + mi) * 4 + ks) * 32 + lane) * 4);
            uint2 bf[4];
#pragma unroll
            for (int nj = 0; nj < 4; nj++)
                bf[nj] = *(const uint2*)(B + (((ntb + nj) * 4 + ks) * 32 + lane) * 2);
#pragma unroll
            for (int mi = 0; mi < 2; mi++)
#pragma unroll
                for (int nj = 0; nj < 4; nj++)
                    mma8(acc[mi][nj], (const uint32_t*)&af[mi], (const uint32_t*)&bf[nj]);
        }
        if (kt + 1 < KT) {
            __syncthreads();
            uint32_t* d = sm + (buf ^ 1) * 8192;
            const float* a0 = &Av0.x; const float* a1 = &Av1.x;
#pragma unroll
            for (int j = 0; j < 4; j++) {
                d[a_s0 + j * 4]     = f2tf(a0[j]);
                d[a_s0 + j * 4 + 2] = f2tf(a1[j]);
            }
            const float* b0 = &Bv0.x; const float* b1 = &Bv1.x;
#pragma unroll
            for (int j = 0; j < 4; j++) {
                d[b_s0 + j * 8]      = f2tf(b0[j]);
                d[b_s0 + 32 + j * 8] = f2tf(b1[j]);
            }
            __syncthreads();
        }
    }

    // ---- SwiGLU epilogue via SMEM exchange ----
    // KT=32 (even) -> final compute read buf1 = sm[8192..16384); sm[0..8192) free.
    float* hx = (float*)sm;              // [128][64]
    if (grp == 1) {                      // w3 results
#pragma unroll
        for (int mi = 0; mi < 2; mi++)
#pragma unroll
            for (int h = 0; h < 2; h++) {
                int row = wm + mi * 16 + r + h * 8;
#pragma unroll
                for (int nj = 0; nj < 4; nj++) {
                    float2 v = make_float2(acc[mi][nj][h * 2], acc[mi][nj][h * 2 + 1]);
                    *(float2*)(hx + row * 64 + wn + nj * 8 + c * 2) = v;
                }
            }
    }
    __syncthreads();
    if (grp == 0) {                      // combine with w1 results
#pragma unroll
        for (int mi = 0; mi < 2; mi++)
#pragma unroll
            for (int h = 0; h < 2; h++) {
                int row = wm + mi * 16 + r + h * 8;
#pragma unroll
                for (int nj = 0; nj < 4; nj++) {
                    float* p = hx + row * 64 + wn + nj * 8 + c * 2;
                    float2 v3 = *(float2*)p;
                    float a0 = acc[mi][nj][h * 2], a1 = acc[mi][nj][h * 2 + 1];
                    float2 o;
                    o.x = a0 / (1.0f + __expf(-a0)) * v3.x;
                    o.y = a1 / (1.0f + __expf(-a1)) * v3.y;
                    *(float2*)p = o;
                }
            }
    }
    __syncthreads();
    // coalesced copy hx -> g_h
#pragma unroll
    for (int ii = 0; ii < 4; ii++) {
        int fi  = tid + ii * 512;        // 0..2047 float4 units
        int row = fi >> 4, quad = fi & 15;
        if (m0 + row < cnt) {
            float* dst = g_h + (size_t)g_pairs[e * T + m0 + row] * F + n0 + quad * 4;
            *(float4*)dst = *(float4*)(hx + row * 64 + quad * 4);
        }
    }
}

// ---------------------------------------------------------------------------
// GEMM2: tile 128(M gathered) x 128(D), K=F (128 k-tiles of 32).
// 16 warps = 4Mx4N, warp tile 32x32. Weighted atomicAdd combine.
// ---------------------------------------------------------------------------
__global__ __launch_bounds__(512, 1)
void gemm2_mma(const float* __restrict__ w2, float* __restrict__ out) {
    int e   = blockIdx.z;
    int cnt = g_counts[e];
    int m0  = blockIdx.x * 128;
    if (m0 >= cnt) return;
    int n0  = blockIdx.y * 128;

    extern __shared__ uint32_t sm[];
    int tid = threadIdx.x;

    // A staging (from g_h)
    int arow = tid >> 2, aq = tid & 3;
    const float* asrc = (m0 + arow < cnt)
        ? g_h + (size_t)g_pairs[e * T + m0 + arow] * F + aq * 8 : nullptr;
    int a_s0 = (((arow >> 4) * 4 + aq) * 32 + (arow & 7) * 4) * 4 + ((arow >> 3) & 1);

    // B staging: w2 [F][D]; 2 float4 each (nq, nq+1)
    int bk  = tid >> 4;                  // 0..31
    int bnq = (tid & 15) * 2;            // even, 0..30
    const float* bmat = w2 + (size_t)e * F * D + n0 + bnq * 4;
    int b_s0 = 4096
             + (((bnq >> 1) * 4 + (bk >> 3)) * 32 + (bk & 3)) * 2 + ((bk >> 2) & 1);

    // compute mapping: 16 warps = 4Mx4N
    int wid = tid >> 5, lane = tid & 31;
    int wm = (wid >> 2) * 32, wn = (wid & 3) * 32;
    int r = lane >> 2, c = lane & 3;
    int mtb = wm >> 4, ntb = wn >> 3;

    float acc[2][4][4];
#pragma unroll
    for (int mi = 0; mi < 2; mi++)
#pragma unroll
        for (int nj = 0; nj < 4; nj++)
#pragma unroll
            for (int q = 0; q < 4; q++) acc[mi][nj][q] = 0.f;

    const int KT = F / 32;               // 128

    float4 Av0, Av1, Bv0, Bv1;
    Av0 = asrc ? *(const float4*)(asrc)     : make_float4(0.f, 0.f, 0.f, 0.f);
    Av1 = asrc ? *(const float4*)(asrc + 4) : make_float4(0.f, 0.f, 0.f, 0.f);
    Bv0 = *(const float4*)(bmat + (size_t)bk * D);
    Bv1 = *(const float4*)(bmat + (size_t)bk * D + 4);
    {
        uint32_t* d = sm;
        const float* a0 = &Av0.x; const float* a1 = &Av1.x;
#pragma unroll
        for (int j = 0; j < 4; j++) {
            d[a_s0 + j * 4]     = f2tf(a0[j]);
            d[a_s0 + j * 4 + 2] = f2tf(a1[j]);
        }
        const float* b0 = &Bv0.x; const float* b1 = &Bv1.x;
#pragma unroll
        for (int j = 0; j < 4; j++) {
            d[b_s0 + j * 8]      = f2tf(b0[j]);
            d[b_s0 + 32 + j * 8] = f2tf(b1[j]);
        }
    }
    __syncthreads();

    for (int kt = 0; kt < KT; kt++) {
        int buf = kt & 1;
        if (kt + 1 < KT) {
            Av0 = asrc ? *(const float4*)(asrc + (kt + 1) * 32)     : make_float4(0.f, 0.f, 0.f, 0.f);
            Av1 = asrc ? *(const float4*)(asrc + (kt + 1) * 32 + 4) : make_float4(0.f, 0.f, 0.f, 0.f);
            Bv0 = *(const float4*)(bmat + (size_t)((kt + 1) * 32 + bk) * D);
            Bv1 = *(const float4*)(bmat + (size_t)((kt + 1) * 32 + bk) * D + 4);
        }
        const uint32_t* A = sm + buf * 8192;
        const uint32_t* B = sm + buf * 8192 + 4096;
#pragma unroll
        for (int ks = 0; ks < 4; ks++) {
            uint4 af[2];
#pragma unroll
            for (int mi = 0; mi < 2; mi++)
                af[mi] = *(const uint4*)(A + (((mtb + mi) * 4 + ks) * 32 + lane) * 4);
            uint2 bf[4];
#pragma unroll
            for (int nj = 0; nj < 4; nj++)
                bf[nj] = *(const uint2*)(B + (((ntb + nj) * 4 + ks) * 32 + lane) * 2);
#pragma unroll
            for (int mi = 0; mi < 2; mi++)
#pragma unroll
                for (int nj = 0; nj < 4; nj++)
                    mma8(acc[mi][nj], (const uint32_t*)&af[mi], (const uint32_t*)&bf[nj]);
        }
        if (kt + 1 < KT) {
            __syncthreads();
            uint32_t* d = sm + (buf ^ 1) * 8192;
            const float* a0 = &Av0.x; const float* a1 = &Av1.x;
#pragma unroll
            for (int j = 0; j < 4; j++) {
                d[a_s0 + j * 4]     = f2tf(a0[j]);
                d[a_s0 + j * 4 + 2] = f2tf(a1[j]);
            }
            const float* b0 = &Bv0.x; const float* b1 = &Bv1.x;
#pragma unroll
            for (int j = 0; j < 4; j++) {
                d[b_s0 + j * 8]      = f2tf(b0[j]);
                d[b_s0 + 32 + j * 8] = f2tf(b1[j]);
            }
            __syncthreads();
        }
    }

    // weighted combine (atomicAdd: commutative -> deterministic)
#pragma unroll
    for (int mi = 0; mi < 2; mi++)
#pragma unroll
        for (int h = 0; h < 2; h++) {
            int m = m0 + wm + mi * 16 + r + h * 8;
            if (m >= cnt) continue;
            int pair = g_pairs[e * T + m];
            float w  = g_pw[e * T + m];
            float* orow = out + (size_t)(pair >> 1) * D + n0;
#pragma unroll
            for (int nj = 0; nj < 4; nj++) {
                int col = wn + nj * 8 + c * 2;
                atomicAdd(orow + col,     w * acc[mi][nj][h * 2]);
                atomicAdd(orow + col + 1, w * acc[mi][nj][h * 2 + 1]);
            }
        }
}

// ---------------------------------------------------------------------------
extern "C" void kernel_launch(void* const* d_in, const int* in_sizes, int n_in,
                              void* d_out, int out_size) {
    const float* x  = (const float*)d_in[0];   // [T, D]
    const float* gw = (const float*)d_in[1];   // [D, E]
    const float* gb = (const float*)d_in[2];   // [E]
    const float* w1 = (const float*)d_in[3];   // [E, D, F]
    const float* w3 = (const float*)d_in[4];   // [E, D, F]
    const float* w2 = (const float*)d_in[5];   // [E, F, D]
    float* out = (float*)d_out;                // [T, D]

    (void)cudaFuncSetAttribute(gemm1_mma, cudaFuncAttributeMaxDynamicSharedMemorySize, G1_SMEM);
    (void)cudaFuncSetAttribute(gemm2_mma, cudaFuncAttributeMaxDynamicSharedMemorySize, G2_SMEM);

    zero_kernel<<<2048, 256>>>(out);
    router_kernel<<<T, 128>>>(x, gw, gb);
    gemm1_mma<<<dim3(T / 128, F / 64, E), 512, G1_SMEM>>>(x, w1, w3);
    gemm2_mma<<<dim3(T / 128, D / 128, E), 512, G2_SMEM>>>(w2, out);
}

// round 14
// speedup vs baseline: 3.1741x; 2.5643x over previous
#include <cuda_runtime.h>
#include <math.h>
#include <stdint.h>

// Problem dims (fixed by reference)
#define T   4096      // tokens = B*S
#define D   1024      // hidden
#define F   4096      // ffn
#define E   8         // experts

// Tiling
#define ASTRIDE 36          // A smem row stride (floats): bank = r*4+c -> conflict-free
#define BSTRIDE 136         // B smem row stride (floats): bank = c*8+r -> conflict-free
#define A_STAGE (128 * ASTRIDE)          // 4608 floats
#define B_STAGE (32 * BSTRIDE)           // 4352 floats
#define STAGE_FL (A_STAGE + B_STAGE)     // 8960 floats
#define STAGE_BYTES (STAGE_FL * 4)       // 35840
#define NSTAGE 3
#define G_SMEM (NSTAGE * STAGE_BYTES)    // 107520 B

// ---------------------------------------------------------------------------
// Scratch (allocation-free: __device__ globals)
// ---------------------------------------------------------------------------
__device__ int   g_counts[E];
__device__ int   g_pairs[E * T];     // packed (token<<1)|slot, grouped per expert
__device__ float g_pw[E * T];        // renormalized routing weight per entry
__device__ float g_h[(size_t)2 * T * F];   // SwiGLU activations per pair

// ---------------------------------------------------------------------------
// helpers (sm_80+ ISA only)
// ---------------------------------------------------------------------------
__device__ __forceinline__ uint32_t f2tf(float f) {
    uint32_t r;
    asm("cvt.rna.tf32.f32 %0, %1;" : "=r"(r) : "f"(f));
    return r;
}
__device__ __forceinline__ void mma8(float* c, const uint32_t* a, const uint32_t* b) {
    asm volatile(
        "mma.sync.aligned.m16n8k8.row.col.f32.tf32.tf32.f32 "
        "{%0,%1,%2,%3}, {%4,%5,%6,%7}, {%8,%9}, {%0,%1,%2,%3};"
        : "+f"(c[0]), "+f"(c[1]), "+f"(c[2]), "+f"(c[3])
        : "r"(a[0]), "r"(a[1]), "r"(a[2]), "r"(a[3]), "r"(b[0]), "r"(b[1]));
}
__device__ __forceinline__ uint32_t cvta_smem(const void* p) {
    uint32_t a;
    asm("{ .reg .u64 t; cvta.to.shared.u64 t, %1; cvt.u32.u64 %0, t; }"
        : "=r"(a) : "l"(p));
    return a;
}
// 16B async copy, src_size 16 (copy) or 0 (zero-fill)
__device__ __forceinline__ void cp16(uint32_t dst, const void* src, int sz) {
    asm volatile("cp.async.cg.shared.global [%0], [%1], 16, %2;"
                 :: "r"(dst), "l"(src), "r"(sz));
}
#define CP_COMMIT() asm volatile("cp.async.commit_group;" ::: "memory")
#define CP_WAIT1()  asm volatile("cp.async.wait_group 1;" ::: "memory")

// ---------------------------------------------------------------------------
// Zero output + counters
// ---------------------------------------------------------------------------
__global__ void zero_kernel(float* __restrict__ out) {
    int idx = blockIdx.x * blockDim.x + threadIdx.x;
    const int total = T * D;
    for (int i = idx; i < total; i += gridDim.x * blockDim.x) out[i] = 0.0f;
    if (idx < E) g_counts[idx] = 0;
}

// ---------------------------------------------------------------------------
// Router (unchanged — known correct)
// ---------------------------------------------------------------------------
__global__ void router_kernel(const float* __restrict__ x,
                              const float* __restrict__ gw,
                              const float* __restrict__ gb) {
    int t   = blockIdx.x;
    int tid = threadIdx.x;              // 128 threads
    __shared__ float s[128][E];

    float acc[E];
#pragma unroll
    for (int e = 0; e < E; e++) acc[e] = 0.0f;

    const float* xr = x + (size_t)t * D;
    for (int d = tid; d < D; d += 128) {
        float xv = xr[d];
#pragma unroll
        for (int e = 0; e < E; e++) acc[e] += xv * gw[d * E + e];
    }
#pragma unroll
    for (int e = 0; e < E; e++) s[tid][e] = acc[e];
    __syncthreads();

    if (tid == 0) {
        float l[E];
#pragma unroll
        for (int e = 0; e < E; e++) {
            float a = 0.0f;
            for (int i = 0; i < 128; i++) a += s[i][e];
            l[e] = a + gb[e];
        }
        int i1 = 0;
        for (int e = 1; e < E; e++) if (l[e] > l[i1]) i1 = e;
        int i2 = -1;
        for (int e = 0; e < E; e++) {
            if (e == i1) continue;
            if (i2 < 0 || l[e] > l[i2]) i2 = e;
        }
        float wb  = expf(l[i2] - l[i1]);
        float w1n = 1.0f / (1.0f + wb);
        float w2n = wb * w1n;

        int p0 = atomicAdd(&g_counts[i1], 1);
        g_pairs[i1 * T + p0] = (t << 1);
        g_pw[i1 * T + p0]    = w1n;
        int p1 = atomicAdd(&g_counts[i2], 1);
        g_pairs[i2 * T + p1] = (t << 1) | 1;
        g_pw[i2 * T + p1]    = w2n;
    }
}

// ===========================================================================
// GEMM1: CTA tile 128(M gathered) x [64(w1) | 64(w3)] stacked as N=128.
// K = D = 1024 (32 k-tiles of 32). 256 thr, 8 warps = 2Mx4N, warp 64x32.
// cp.async 3-stage pipeline. SwiGLU via smem exchange epilogue -> g_h.
// ===========================================================================
__global__ __launch_bounds__(256, 2)
void gemm1_mma(const float* __restrict__ x,
               const float* __restrict__ w1,
               const float* __restrict__ w3) {
    int e   = blockIdx.z;
    int cnt = g_counts[e];
    int m0  = blockIdx.x * 128;
    if (m0 >= cnt) return;
    int n0  = blockIdx.y * 64;

    extern __shared__ float sm[];
    uint32_t smb = cvta_smem(sm);
    int tid = threadIdx.x;

    const float* w1p = w1 + (size_t)e * D * F;
    const float* w3p = w3 + (size_t)e * D * F;

    // ---- staging precompute: A (4 chunks), B (4 chunks) per thread ----
    const float* asrc[4]; int asz[4]; uint32_t adst[4];
    int aq = tid & 7;
#pragma unroll
    for (int i = 0; i < 4; i++) {
        int row = (tid >> 3) + i * 32;
        adst[i] = (uint32_t)((row * ASTRIDE + aq * 4) * 4);
        if (m0 + row < cnt) {
            asrc[i] = x + (size_t)(g_pairs[e * T + m0 + row] >> 1) * D + aq * 4;
            asz[i] = 16;
        } else { asrc[i] = x; asz[i] = 0; }
    }
    const float* bsrc[4]; uint32_t bdst[4];
#pragma unroll
    for (int i = 0; i < 4; i++) {
        int chunk = tid + i * 256;       // 0..1023
        int mat = chunk >> 9, rem = chunk & 511;
        int k = rem >> 4, nq = rem & 15;
        bdst[i] = (uint32_t)((A_STAGE + k * BSTRIDE + mat * 64 + nq * 4) * 4);
        bsrc[i] = (mat ? w3p : w1p) + (size_t)k * F + n0 + nq * 4;
    }

    // ---- compute mapping: 8 warps = 2M x 4N(stacked), warp tile 64x32 ----
    int wid = tid >> 5, lane = tid & 31;
    int wm = (wid >> 2) * 64;
    int wn = (wid & 3) * 32;             // stacked col base 0..96
    int r = lane >> 2, c = lane & 3;

    float acc[4][4][4];
#pragma unroll
    for (int mi = 0; mi < 4; mi++)
#pragma unroll
        for (int nj = 0; nj < 4; nj++)
#pragma unroll
            for (int q = 0; q < 4; q++) acc[mi][nj][q] = 0.f;

    const int KT = D / 32;               // 32

    // prologue: stage 0, 1
#pragma unroll
    for (int st = 0; st < 2; st++) {
        uint32_t sb = smb + st * STAGE_BYTES;
#pragma unroll
        for (int i = 0; i < 4; i++) cp16(sb + adst[i], asrc[i] + st * 32, asz[i]);
#pragma unroll
        for (int i = 0; i < 4; i++) cp16(sb + bdst[i], bsrc[i] + (size_t)st * 32 * F, 16);
        CP_COMMIT();
    }

    int stage = 0;
    for (int kt = 0; kt < KT; kt++) {
        CP_WAIT1();
        __syncthreads();
        if (kt + 2 < KT) {
            int ns = (kt + 2) % NSTAGE;
            uint32_t sb = smb + ns * STAGE_BYTES;
#pragma unroll
            for (int i = 0; i < 4; i++) cp16(sb + adst[i], asrc[i] + (kt + 2) * 32, asz[i]);
#pragma unroll
            for (int i = 0; i < 4; i++) cp16(sb + bdst[i], bsrc[i] + (size_t)(kt + 2) * 32 * F, 16);
        }
        CP_COMMIT();

        const float* As = sm + stage * STAGE_FL;
        const float* Bs = As + A_STAGE;
#pragma unroll
        for (int ks = 0; ks < 4; ks++) {
            int kc = ks * 8 + c;
            uint32_t af[4][4];
#pragma unroll
            for (int mi = 0; mi < 4; mi++) {
                int row = wm + mi * 16 + r;
                af[mi][0] = f2tf(As[row * ASTRIDE + kc]);
                af[mi][1] = f2tf(As[(row + 8) * ASTRIDE + kc]);
                af[mi][2] = f2tf(As[row * ASTRIDE + kc + 4]);
                af[mi][3] = f2tf(As[(row + 8) * ASTRIDE + kc + 4]);
            }
            uint32_t bf[4][2];
#pragma unroll
            for (int nj = 0; nj < 4; nj++) {
                int n = wn + nj * 8 + r;
                bf[nj][0] = f2tf(Bs[kc * BSTRIDE + n]);
                bf[nj][1] = f2tf(Bs[(kc + 4) * BSTRIDE + n]);
            }
#pragma unroll
            for (int mi = 0; mi < 4; mi++)
#pragma unroll
                for (int nj = 0; nj < 4; nj++)
                    mma8(acc[mi][nj], af[mi], bf[nj]);
        }
        stage = (stage + 1) % NSTAGE;
    }

    // ---- SwiGLU epilogue via smem exchange (reuses stage memory) ----
    __syncthreads();                     // all compute reads of smem done
    float* hx = sm;                      // [128][132], stacked cols 0..127
#pragma unroll
    for (int mi = 0; mi < 4; mi++)
#pragma unroll
        for (int h = 0; h < 2; h++) {
            int m = wm + mi * 16 + r + h * 8;
#pragma unroll
            for (int nj = 0; nj < 4; nj++) {
                int col = wn + nj * 8 + c * 2;
                *(float2*)&hx[m * 132 + col] =
                    make_float2(acc[mi][nj][h * 2], acc[mi][nj][h * 2 + 1]);
            }
        }
    __syncthreads();
#pragma unroll
    for (int i = 0; i < 8; i++) {
        int fi = tid + i * 256;          // 0..2047 float4 units over 128x64
        int row = fi >> 4, q = fi & 15;
        if (m0 + row < cnt) {
            float4 v1 = *(float4*)&hx[row * 132 + q * 4];
            float4 v3 = *(float4*)&hx[row * 132 + 64 + q * 4];
            float4 o;
            o.x = v1.x / (1.0f + __expf(-v1.x)) * v3.x;
            o.y = v1.y / (1.0f + __expf(-v1.y)) * v3.y;
            o.z = v1.z / (1.0f + __expf(-v1.z)) * v3.z;
            o.w = v1.w / (1.0f + __expf(-v1.w)) * v3.w;
            *(float4*)(g_h + (size_t)g_pairs[e * T + m0 + row] * F + n0 + q * 4) = o;
        }
    }
}

// ===========================================================================
// GEMM2: CTA tile 128(M gathered) x 128(D). K = F = 4096 (128 k-tiles).
// 256 thr, 8 warps = 2Mx4N, warp tile 64x32. cp.async 3-stage pipeline.
// Weighted atomicAdd combine epilogue.
// ===========================================================================
__global__ __launch_bounds__(256, 2)
void gemm2_mma(const float* __restrict__ w2, float* __restrict__ out) {
    int e   = blockIdx.z;
    int cnt = g_counts[e];
    int m0  = blockIdx.x * 128;
    if (m0 >= cnt) return;
    int n0  = blockIdx.y * 128;

    extern __shared__ float sm[];
    uint32_t smb = cvta_smem(sm);
    int tid = threadIdx.x;

    const float* w2p = w2 + (size_t)e * F * D;

    const float* asrc[4]; int asz[4]; uint32_t adst[4];
    int aq = tid & 7;
#pragma unroll
    for (int i = 0; i < 4; i++) {
        int row = (tid >> 3) + i * 32;
        adst[i] = (uint32_t)((row * ASTRIDE + aq * 4) * 4);
        if (m0 + row < cnt) {
            asrc[i] = g_h + (size_t)g_pairs[e * T + m0 + row] * F + aq * 4;
            asz[i] = 16;
        } else { asrc[i] = g_h; asz[i] = 0; }
    }
    const float* bsrc[4]; uint32_t bdst[4];
#pragma unroll
    for (int i = 0; i < 4; i++) {
        int chunk = tid + i * 256;       // 0..1023
        int k = chunk >> 5, nq = chunk & 31;
        bdst[i] = (uint32_t)((A_STAGE + k * BSTRIDE + nq * 4) * 4);
        bsrc[i] = w2p + (size_t)k * D + n0 + nq * 4;
    }

    int wid = tid >> 5, lane = tid & 31;
    int wm = (wid >> 2) * 64;
    int wn = (wid & 3) * 32;
    int r = lane >> 2, c = lane & 3;

    float acc[4][4][4];
#pragma unroll
    for (int mi = 0; mi < 4; mi++)
#pragma unroll
        for (int nj = 0; nj < 4; nj++)
#pragma unroll
            for (int q = 0; q < 4; q++) acc[mi][nj][q] = 0.f;

    const int KT = F / 32;               // 128

#pragma unroll
    for (int st = 0; st < 2; st++) {
        uint32_t sb = smb + st * STAGE_BYTES;
#pragma unroll
        for (int i = 0; i < 4; i++) cp16(sb + adst[i], asrc[i] + st * 32, asz[i]);
#pragma unroll
        for (int i = 0; i < 4; i++) cp16(sb + bdst[i], bsrc[i] + (size_t)st * 32 * D, 16);
        CP_COMMIT();
    }

    int stage = 0;
    for (int kt = 0; kt < KT; kt++) {
        CP_WAIT1();
        __syncthreads();
        if (kt + 2 < KT) {
            int ns = (kt + 2) % NSTAGE;
            uint32_t sb = smb + ns * STAGE_BYTES;
#pragma unroll
            for (int i = 0; i < 4; i++) cp16(sb + adst[i], asrc[i] + (kt + 2) * 32, asz[i]);
#pragma unroll
            for (int i = 0; i < 4; i++) cp16(sb + bdst[i], bsrc[i] + (size_t)(kt + 2) * 32 * D, 16);
        }
        CP_COMMIT();

        const float* As = sm + stage * STAGE_FL;
        const float* Bs = As + A_STAGE;
#pragma unroll
        for (int ks = 0; ks < 4; ks++) {
            int kc = ks * 8 + c;
            uint32_t af[4][4];
#pragma unroll
            for (int mi = 0; mi < 4; mi++) {
                int row = wm + mi * 16 + r;
                af[mi][0] = f2tf(As[row * ASTRIDE + kc]);
                af[mi][1] = f2tf(As[(row + 8) * ASTRIDE + kc]);
                af[mi][2] = f2tf(As[row * ASTRIDE + kc + 4]);
                af[mi][3] = f2tf(As[(row + 8) * ASTRIDE + kc + 4]);
            }
            uint32_t bf[4][2];
#pragma unroll
            for (int nj = 0; nj < 4; nj++) {
                int n = wn + nj * 8 + r;
                bf[nj][0] = f2tf(Bs[kc * BSTRIDE + n]);
                bf[nj][1] = f2tf(Bs[(kc + 4) * BSTRIDE + n]);
            }
#pragma unroll
            for (int mi = 0; mi < 4; mi++)
#pragma unroll
                for (int nj = 0; nj < 4; nj++)
                    mma8(acc[mi][nj], af[mi], bf[nj]);
        }
        stage = (stage + 1) % NSTAGE;
    }

    // weighted combine (atomicAdd: commutative -> deterministic)
#pragma unroll
    for (int mi = 0; mi < 4; mi++)
#pragma unroll
        for (int h = 0; h < 2; h++) {
            int m = m0 + wm + mi * 16 + r + h * 8;
            if (m >= cnt) continue;
            int pair = g_pairs[e * T + m];
            float w  = g_pw[e * T + m];
            float* orow = out + (size_t)(pair >> 1) * D + n0;
#pragma unroll
            for (int nj = 0; nj < 4; nj++) {
                int col = wn + nj * 8 + c * 2;
                atomicAdd(orow + col,     w * acc[mi][nj][h * 2]);
                atomicAdd(orow + col + 1, w * acc[mi][nj][h * 2 + 1]);
            }
        }
}

// ---------------------------------------------------------------------------
extern "C" void kernel_launch(void* const* d_in, const int* in_sizes, int n_in,
                              void* d_out, int out_size) {
    const float* x  = (const float*)d_in[0];   // [T, D]
    const float* gw = (const float*)d_in[1];   // [D, E]
    const float* gb = (const float*)d_in[2];   // [E]
    const float* w1 = (const float*)d_in[3];   // [E, D, F]
    const float* w3 = (const float*)d_in[4];   // [E, D, F]
    const float* w2 = (const float*)d_in[5];   // [E, F, D]
    float* out = (float*)d_out;                // [T, D]

    (void)cudaFuncSetAttribute(gemm1_mma, cudaFuncAttributeMaxDynamicSharedMemorySize, G_SMEM);
    (void)cudaFuncSetAttribute(gemm2_mma, cudaFuncAttributeMaxDynamicSharedMemorySize, G_SMEM);

    zero_kernel<<<2048, 256>>>(out);
    router_kernel<<<T, 128>>>(x, gw, gb);
    gemm1_mma<<<dim3(T / 128, F / 64, E), 256, G_SMEM>>>(x, w1, w3);
    gemm2_mma<<<dim3(T / 128, D / 128, E), 256, G_SMEM>>>(w2, out);
}

// round 15
// speedup vs baseline: 3.6009x; 1.1344x over previous
#include <cuda_runtime.h>
#include <math.h>
#include <stdint.h>

// Problem dims (fixed by reference)
#define T   4096      // tokens = B*S
#define D   1024      // hidden
#define F   4096      // ffn
#define E   8         // experts

// Tiling
#define ASTRIDE 36                       // A smem row stride (floats), conflict-free
#define A_STAGE (128 * ASTRIDE)          // 4608 floats
#define B_STAGE 4096                     // packed B tile (32k x 128n), linear
#define STAGE_FL (A_STAGE + B_STAGE)     // 8704 floats
#define STAGE_BYTES (STAGE_FL * 4)       // 34816
#define NSTAGE 3
#define G_SMEM (NSTAGE * STAGE_BYTES)    // 104448 B

// ---------------------------------------------------------------------------
// Scratch (allocation-free: __device__ globals)
// ---------------------------------------------------------------------------
__device__ int   g_counts[E];
__device__ int   g_pairs[E * T];
__device__ float g_pw[E * T];
__device__ float g_h[(size_t)2 * T * F];            // SwiGLU acts (tf32-rounded)
__device__ float g_xt[(size_t)T * D];               // tf32-rounded x
__device__ float g_w13[(size_t)E * 64 * 32 * 4096]; // packed w1|w3 tiles
__device__ float g_w2p[(size_t)E * 8 * 128 * 4096]; // packed w2 tiles

// ---------------------------------------------------------------------------
// helpers (sm_80+ ISA only)
// ---------------------------------------------------------------------------
__device__ __forceinline__ uint32_t f2tf(float f) {
    uint32_t r;
    asm("cvt.rna.tf32.f32 %0, %1;" : "=r"(r) : "f"(f));
    return r;
}
__device__ __forceinline__ float tfr(float f) { return __uint_as_float(f2tf(f)); }

__device__ __forceinline__ void mma8(float* c, const uint32_t* a, const uint32_t* b) {
    asm volatile(
        "mma.sync.aligned.m16n8k8.row.col.f32.tf32.tf32.f32 "
        "{%0,%1,%2,%3}, {%4,%5,%6,%7}, {%8,%9}, {%0,%1,%2,%3};"
        : "+f"(c[0]), "+f"(c[1]), "+f"(c[2]), "+f"(c[3])
        : "r"(a[0]), "r"(a[1]), "r"(a[2]), "r"(a[3]), "r"(b[0]), "r"(b[1]));
}
__device__ __forceinline__ uint32_t cvta_smem(const void* p) {
    uint32_t a;
    asm("{ .reg .u64 t; cvta.to.shared.u64 t, %1; cvt.u32.u64 %0, t; }"
        : "=r"(a) : "l"(p));
    return a;
}
__device__ __forceinline__ void cp16(uint32_t dst, const void* src, int sz) {
    asm volatile("cp.async.cg.shared.global [%0], [%1], 16, %2;"
                 :: "r"(dst), "l"(src), "r"(sz));
}
#define CP_COMMIT() asm volatile("cp.async.commit_group;" ::: "memory")
#define CP_WAIT1()  asm volatile("cp.async.wait_group 1;" ::: "memory")

// ---------------------------------------------------------------------------
// Zero output + counters
// ---------------------------------------------------------------------------
__global__ void zero_kernel(float* __restrict__ out) {
    int idx = blockIdx.x * blockDim.x + threadIdx.x;
    const int total = T * D;
    for (int i = idx; i < total; i += gridDim.x * blockDim.x) out[i] = 0.0f;
    if (idx < E) g_counts[idx] = 0;
}

// ---------------------------------------------------------------------------
// Prepass: tf32-round x
// ---------------------------------------------------------------------------
__global__ void pack_x(const float* __restrict__ x) {
    int i = blockIdx.x * blockDim.x + threadIdx.x;
    const int tot = T * D / 4;
    for (; i < tot; i += gridDim.x * blockDim.x) {
        float4 v = ((const float4*)x)[i];
        v.x = tfr(v.x); v.y = tfr(v.y); v.z = tfr(v.z); v.w = tfr(v.w);
        ((float4*)g_xt)[i] = v;
    }
}

// ---------------------------------------------------------------------------
// Prepass: pack w1|w3 into mma-B-fragment order, tf32-rounded.
// Layout: [e][nt(64)][kt(32)][wg(4)][ks(4)][32 slots x 8 floats] (tile=4096 fl)
// wg 0,1 -> w1 cols (wg&1)*32..+31 of the 64-n tile; wg 2,3 -> w3.
// Slot swizzle: physical uint4 ph at lane*2+ph holds logical j = ph ^ (r&1).
// Logical j=0 -> {nj0:(k,k+4), nj1:(k,k+4)}, j=1 -> {nj2, nj3}.
// ---------------------------------------------------------------------------
__global__ void pack_w13(const float* __restrict__ w1, const float* __restrict__ w3) {
    size_t i4 = (size_t)blockIdx.x * blockDim.x + threadIdx.x;
    const size_t tot = (size_t)E * 64 * 32 * 4096 / 4;
    for (; i4 < tot; i4 += (size_t)gridDim.x * blockDim.x) {
        uint32_t p4 = (uint32_t)(i4 & 63);
        uint32_t ks = (uint32_t)((i4 >> 6) & 3);
        uint32_t wg = (uint32_t)((i4 >> 8) & 3);
        uint32_t kt = (uint32_t)((i4 >> 10) & 31);
        uint32_t nt = (uint32_t)((i4 >> 15) & 63);
        uint32_t e  = (uint32_t)(i4 >> 21);
        uint32_t lane = p4 >> 1, ph = p4 & 1;
        uint32_t r = lane >> 2, c = lane & 3;
        uint32_t j = ph ^ (r & 1);
        const float* src = (wg >= 2 ? w3 : w1) + (size_t)e * D * F;
        int colb = nt * 64 + (wg & 1) * 32 + r;
        int kb   = kt * 32 + ks * 8 + c;
        float4 v; float* vp = &v.x;
#pragma unroll
        for (int q = 0; q < 4; q++) {
            int nj = (j << 1) + (q >> 1);
            int k  = kb + (q & 1) * 4;
            vp[q] = tfr(src[(size_t)k * F + colb + nj * 8]);
        }
        ((float4*)g_w13)[i4] = v;
    }
}

// ---------------------------------------------------------------------------
// Prepass: pack w2. Layout: [e][nt(8)][kt(128)][wg(4)][ks(4)][32x8]
// wg covers n (nt*128 + wg*32 ..); k over F.
// ---------------------------------------------------------------------------
__global__ void pack_w2(const float* __restrict__ w2) {
    size_t i4 = (size_t)blockIdx.x * blockDim.x + threadIdx.x;
    const size_t tot = (size_t)E * 8 * 128 * 4096 / 4;
    for (; i4 < tot; i4 += (size_t)gridDim.x * blockDim.x) {
        uint32_t p4 = (uint32_t)(i4 & 63);
        uint32_t ks = (uint32_t)((i4 >> 6) & 3);
        uint32_t wg = (uint32_t)((i4 >> 8) & 3);
        uint32_t kt = (uint32_t)((i4 >> 10) & 127);
        uint32_t nt = (uint32_t)((i4 >> 17) & 7);
        uint32_t e  = (uint32_t)(i4 >> 20);
        uint32_t lane = p4 >> 1, ph = p4 & 1;
        uint32_t r = lane >> 2, c = lane & 3;
        uint32_t j = ph ^ (r & 1);
        const float* src = w2 + (size_t)e * F * D;
        int colb = nt * 128 + wg * 32 + r;
        int kb   = kt * 32 + ks * 8 + c;
        float4 v; float* vp = &v.x;
#pragma unroll
        for (int q = 0; q < 4; q++) {
            int nj = (j << 1) + (q >> 1);
            int k  = kb + (q & 1) * 4;
            vp[q] = tfr(src[(size_t)k * D + colb + nj * 8]);
        }
        ((float4*)g_w2p)[i4] = v;
    }
}

// ---------------------------------------------------------------------------
// Router (unchanged — known correct)
// ---------------------------------------------------------------------------
__global__ void router_kernel(const float* __restrict__ x,
                              const float* __restrict__ gw,
                              const float* __restrict__ gb) {
    int t   = blockIdx.x;
    int tid = threadIdx.x;
    __shared__ float s[128][E];

    float acc[E];
#pragma unroll
    for (int e = 0; e < E; e++) acc[e] = 0.0f;

    const float* xr = x + (size_t)t * D;
    for (int d = tid; d < D; d += 128) {
        float xv = xr[d];
#pragma unroll
        for (int e = 0; e < E; e++) acc[e] += xv * gw[d * E + e];
    }
#pragma unroll
    for (int e = 0; e < E; e++) s[tid][e] = acc[e];
    __syncthreads();

    if (tid == 0) {
        float l[E];
#pragma unroll
        for (int e = 0; e < E; e++) {
            float a = 0.0f;
            for (int i = 0; i < 128; i++) a += s[i][e];
            l[e] = a + gb[e];
        }
        int i1 = 0;
        for (int e = 1; e < E; e++) if (l[e] > l[i1]) i1 = e;
        int i2 = -1;
        for (int e = 0; e < E; e++) {
            if (e == i1) continue;
            if (i2 < 0 || l[e] > l[i2]) i2 = e;
        }
        float wb  = expf(l[i2] - l[i1]);
        float w1n = 1.0f / (1.0f + wb);
        float w2n = wb * w1n;

        int p0 = atomicAdd(&g_counts[i1], 1);
        g_pairs[i1 * T + p0] = (t << 1);
        g_pw[i1 * T + p0]    = w1n;
        int p1 = atomicAdd(&g_counts[i2], 1);
        g_pairs[i2 * T + p1] = (t << 1) | 1;
        g_pw[i2 * T + p1]    = w2n;
    }
}

// ===========================================================================
// GEMM1: CTA tile 128(M gathered) x [64(w1)|64(w3)] stacked N=128.
// K = D (32 k-tiles). 256 thr, 8 warps = 2Mx4N, warp 64x32.
// cp.async 3-stage. No cvt in loop (pre-rounded operands, packed B).
// ===========================================================================
__global__ __launch_bounds__(256, 2)
void gemm1_mma(const float* __restrict__ dummy) {
    int e   = blockIdx.z;
    int cnt = g_counts[e];
    int m0  = blockIdx.x * 128;
    if (m0 >= cnt) return;
    int n0  = blockIdx.y * 64;

    extern __shared__ float sm[];
    uint32_t smb = cvta_smem(sm);
    int tid = threadIdx.x;

    // A staging: 4 chunks/thread from g_xt (gathered rows)
    const float* asrc[4]; int asz[4]; uint32_t adst[4];
    int aq = tid & 7;
#pragma unroll
    for (int i = 0; i < 4; i++) {
        int row = (tid >> 3) + i * 32;
        adst[i] = (uint32_t)((row * ASTRIDE + aq * 4) * 4);
        if (m0 + row < cnt) {
            asrc[i] = g_xt + (size_t)(g_pairs[e * T + m0 + row] >> 1) * D + aq * 4;
            asz[i] = 16;
        } else { asrc[i] = g_xt; asz[i] = 0; }
    }
    // B staging: linear copy of packed tile
    const float* bbase = g_w13 + (size_t)(e * 64 + blockIdx.y) * 32 * 4096;
    uint32_t bdst[4]; int bofs[4];
#pragma unroll
    for (int i = 0; i < 4; i++) {
        int chunk = tid + i * 256;
        bdst[i] = (uint32_t)((A_STAGE + chunk * 4) * 4);
        bofs[i] = chunk * 4;
    }

    // compute mapping: 8 warps = 2M x 4N(stacked), warp tile 64x32
    int wid = tid >> 5, lane = tid & 31;
    int wm = (wid >> 2) * 64;
    int wgq = wid & 3;                   // N warp-group (packed B index)
    int wn = wgq * 32;
    int r = lane >> 2, c = lane & 3;
    int xs = (lane & 4) ? 4 : 0;         // B swizzle offset
    int bwoff = (wgq << 10) + lane * 8;  // within-tile B base for this thread

    float acc[4][4][4];
#pragma unroll
    for (int mi = 0; mi < 4; mi++)
#pragma unroll
        for (int nj = 0; nj < 4; nj++)
#pragma unroll
            for (int q = 0; q < 4; q++) acc[mi][nj][q] = 0.f;

    const int KT = D / 32;               // 32

#pragma unroll
    for (int st = 0; st < 2; st++) {
        uint32_t sb = smb + st * STAGE_BYTES;
#pragma unroll
        for (int i = 0; i < 4; i++) cp16(sb + adst[i], asrc[i] + st * 32, asz[i]);
#pragma unroll
        for (int i = 0; i < 4; i++) cp16(sb + bdst[i], bbase + (size_t)st * 4096 + bofs[i], 16);
        CP_COMMIT();
    }

    int stage = 0;
    for (int kt = 0; kt < KT; kt++) {
        CP_WAIT1();
        __syncthreads();
        if (kt + 2 < KT) {
            int ns = (kt + 2) % NSTAGE;
            uint32_t sb = smb + ns * STAGE_BYTES;
#pragma unroll
            for (int i = 0; i < 4; i++) cp16(sb + adst[i], asrc[i] + (kt + 2) * 32, asz[i]);
#pragma unroll
            for (int i = 0; i < 4; i++) cp16(sb + bdst[i], bbase + (size_t)(kt + 2) * 4096 + bofs[i], 16);
        }
        CP_COMMIT();

        const float* As = sm + stage * STAGE_FL;
        const float* Bs = As + A_STAGE;
#pragma unroll
        for (int ks = 0; ks < 4; ks++) {
            int kc = ks * 8 + c;
            uint32_t af[4][4];
#pragma unroll
            for (int mi = 0; mi < 4; mi++) {
                int row = wm + mi * 16 + r;
                af[mi][0] = __float_as_uint(As[row * ASTRIDE + kc]);
                af[mi][1] = __float_as_uint(As[(row + 8) * ASTRIDE + kc]);
                af[mi][2] = __float_as_uint(As[row * ASTRIDE + kc + 4]);
                af[mi][3] = __float_as_uint(As[(row + 8) * ASTRIDE + kc + 4]);
            }
            const float* Bks = Bs + bwoff + (ks << 8);
            uint4 b01 = *(const uint4*)(Bks + xs);
            uint4 b23 = *(const uint4*)(Bks + (xs ^ 4));
#pragma unroll
            for (int mi = 0; mi < 4; mi++) {
                mma8(acc[mi][0], af[mi], (const uint32_t*)&b01);
                mma8(acc[mi][1], af[mi], ((const uint32_t*)&b01) + 2);
                mma8(acc[mi][2], af[mi], (const uint32_t*)&b23);
                mma8(acc[mi][3], af[mi], ((const uint32_t*)&b23) + 2);
            }
        }
        stage = (stage + 1) % NSTAGE;
    }

    // ---- SwiGLU epilogue via smem exchange (tf32-rounded store) ----
    __syncthreads();
    float* hx = sm;                      // [128][132]
#pragma unroll
    for (int mi = 0; mi < 4; mi++)
#pragma unroll
        for (int h = 0; h < 2; h++) {
            int m = wm + mi * 16 + r + h * 8;
#pragma unroll
            for (int nj = 0; nj < 4; nj++) {
                int col = wn + nj * 8 + c * 2;
                *(float2*)&hx[m * 132 + col] =
                    make_float2(acc[mi][nj][h * 2], acc[mi][nj][h * 2 + 1]);
            }
        }
    __syncthreads();
#pragma unroll
    for (int i = 0; i < 8; i++) {
        int fi = tid + i * 256;
        int row = fi >> 4, q = fi & 15;
        if (m0 + row < cnt) {
            float4 v1 = *(float4*)&hx[row * 132 + q * 4];
            float4 v3 = *(float4*)&hx[row * 132 + 64 + q * 4];
            float4 o;
            o.x = tfr(v1.x / (1.0f + __expf(-v1.x)) * v3.x);
            o.y = tfr(v1.y / (1.0f + __expf(-v1.y)) * v3.y);
            o.z = tfr(v1.z / (1.0f + __expf(-v1.z)) * v3.z);
            o.w = tfr(v1.w / (1.0f + __expf(-v1.w)) * v3.w);
            *(float4*)(g_h + (size_t)g_pairs[e * T + m0 + row] * F + n0 + q * 4) = o;
        }
    }
}

// ===========================================================================
// GEMM2: CTA tile 128(M gathered) x 128(D). K = F (128 k-tiles).
// Same structure; A from g_h (pre-rounded), B from packed w2.
// ===========================================================================
__global__ __launch_bounds__(256, 2)
void gemm2_mma(float* __restrict__ out) {
    int e   = blockIdx.z;
    int cnt = g_counts[e];
    int m0  = blockIdx.x * 128;
    if (m0 >= cnt) return;
    int n0  = blockIdx.y * 128;

    extern __shared__ float sm[];
    uint32_t smb = cvta_smem(sm);
    int tid = threadIdx.x;

    const float* asrc[4]; int asz[4]; uint32_t adst[4];
    int aq = tid & 7;
#pragma unroll
    for (int i = 0; i < 4; i++) {
        int row = (tid >> 3) + i * 32;
        adst[i] = (uint32_t)((row * ASTRIDE + aq * 4) * 4);
        if (m0 + row < cnt) {
            asrc[i] = g_h + (size_t)g_pairs[e * T + m0 + row] * F + aq * 4;
            asz[i] = 16;
        } else { asrc[i] = g_h; asz[i] = 0; }
    }
    const float* bbase = g_w2p + (size_t)(e * 8 + blockIdx.y) * 128 * 4096;
    uint32_t bdst[4]; int bofs[4];
#pragma unroll
    for (int i = 0; i < 4; i++) {
        int chunk = tid + i * 256;
        bdst[i] = (uint32_t)((A_STAGE + chunk * 4) * 4);
        bofs[i] = chunk * 4;
    }

    int wid = tid >> 5, lane = tid & 31;
    int wm = (wid >> 2) * 64;
    int wgq = wid & 3;
    int wn = wgq * 32;
    int r = lane >> 2, c = lane & 3;
    int xs = (lane & 4) ? 4 : 0;
    int bwoff = (wgq << 10) + lane * 8;

    float acc[4][4][4];
#pragma unroll
    for (int mi = 0; mi < 4; mi++)
#pragma unroll
        for (int nj = 0; nj < 4; nj++)
#pragma unroll
            for (int q = 0; q < 4; q++) acc[mi][nj][q] = 0.f;

    const int KT = F / 32;               // 128

#pragma unroll
    for (int st = 0; st < 2; st++) {
        uint32_t sb = smb + st * STAGE_BYTES;
#pragma unroll
        for (int i = 0; i < 4; i++) cp16(sb + adst[i], asrc[i] + st * 32, asz[i]);
#pragma unroll
        for (int i = 0; i < 4; i++) cp16(sb + bdst[i], bbase + (size_t)st * 4096 + bofs[i], 16);
        CP_COMMIT();
    }

    int stage = 0;
    for (int kt = 0; kt < KT; kt++) {
        CP_WAIT1();
        __syncthreads();
        if (kt + 2 < KT) {
            int ns = (kt + 2) % NSTAGE;
            uint32_t sb = smb + ns * STAGE_BYTES;
#pragma unroll
            for (int i = 0; i < 4; i++) cp16(sb + adst[i], asrc[i] + (kt + 2) * 32, asz[i]);
#pragma unroll
            for (int i = 0; i < 4; i++) cp16(sb + bdst[i], bbase + (size_t)(kt + 2) * 4096 + bofs[i], 16);
        }
        CP_COMMIT();

        const float* As = sm + stage * STAGE_FL;
        const float* Bs = As + A_STAGE;
#pragma unroll
        for (int ks = 0; ks < 4; ks++) {
            int kc = ks * 8 + c;
            uint32_t af[4][4];
#pragma unroll
            for (int mi = 0; mi < 4; mi++) {
                int row = wm + mi * 16 + r;
                af[mi][0] = __float_as_uint(As[row * ASTRIDE + kc]);
                af[mi][1] = __float_as_uint(As[(row + 8) * ASTRIDE + kc]);
                af[mi][2] = __float_as_uint(As[row * ASTRIDE + kc + 4]);
                af[mi][3] = __float_as_uint(As[(row + 8) * ASTRIDE + kc + 4]);
            }
            const float* Bks = Bs + bwoff + (ks << 8);
            uint4 b01 = *(const uint4*)(Bks + xs);
            uint4 b23 = *(const uint4*)(Bks + (xs ^ 4));
#pragma unroll
            for (int mi = 0; mi < 4; mi++) {
                mma8(acc[mi][0], af[mi], (const uint32_t*)&b01);
                mma8(acc[mi][1], af[mi], ((const uint32_t*)&b01) + 2);
                mma8(acc[mi][2], af[mi], (const uint32_t*)&b23);
                mma8(acc[mi][3], af[mi], ((const uint32_t*)&b23) + 2);
            }
        }
        stage = (stage + 1) % NSTAGE;
    }

    // weighted combine (atomicAdd: commutative -> deterministic)
#pragma unroll
    for (int mi = 0; mi < 4; mi++)
#pragma unroll
        for (int h = 0; h < 2; h++) {
            int m = m0 + wm + mi * 16 + r + h * 8;
            if (m >= cnt) continue;
            int pair = g_pairs[e * T + m];
            float w  = g_pw[e * T + m];
            float* orow = out + (size_t)(pair >> 1) * D + n0;
#pragma unroll
            for (int nj = 0; nj < 4; nj++) {
                int col = wn + nj * 8 + c * 2;
                atomicAdd(orow + col,     w * acc[mi][nj][h * 2]);
                atomicAdd(orow + col + 1, w * acc[mi][nj][h * 2 + 1]);
            }
        }
}

// ---------------------------------------------------------------------------
extern "C" void kernel_launch(void* const* d_in, const int* in_sizes, int n_in,
                              void* d_out, int out_size) {
    const float* x  = (const float*)d_in[0];   // [T, D]
    const float* gw = (const float*)d_in[1];   // [D, E]
    const float* gb = (const float*)d_in[2];   // [E]
    const float* w1 = (const float*)d_in[3];   // [E, D, F]
    const float* w3 = (const float*)d_in[4];   // [E, D, F]
    const float* w2 = (const float*)d_in[5];   // [E, F, D]
    float* out = (float*)d_out;                // [T, D]

    (void)cudaFuncSetAttribute(gemm1_mma, cudaFuncAttributeMaxDynamicSharedMemorySize, G_SMEM);
    (void)cudaFuncSetAttribute(gemm2_mma, cudaFuncAttributeMaxDynamicSharedMemorySize, G_SMEM);

    zero_kernel<<<2048, 256>>>(out);
    pack_x<<<1024, 256>>>(x);
    pack_w13<<<8192, 256>>>(w1, w3);
    pack_w2<<<8192, 256>>>(w2);
    router_kernel<<<T, 128>>>(x, gw, gb);
    gemm1_mma<<<dim3(T / 128, F / 64, E), 256, G_SMEM>>>(nullptr);
    gemm2_mma<<<dim3(T / 128, D / 128, E), 256, G_SMEM>>>(out);
}

// round 16
// speedup vs baseline: 3.9294x; 1.0912x over previous
#include <cuda_runtime.h>
#include <math.h>
#include <stdint.h>

// Problem dims (fixed by reference)
#define T   4096      // tokens = B*S
#define D   1024      // hidden
#define F   4096      // ffn
#define E   8         // experts

// Tiling
#define A_STAGE 4096                     // packed A tile (128m x 32k), linear
#define B_STAGE 4096                     // packed B tile (32k x 128n), linear
#define STAGE_FL (A_STAGE + B_STAGE)     // 8192 floats
#define STAGE_BYTES (STAGE_FL * 4)       // 32768
#define NSTAGE 3
#define G_SMEM (NSTAGE * STAGE_BYTES)    // 98304 B

#define ATILE_FL  (32 * 4096)            // per-(e,mtile) packed A: 131072 floats
#define HTILE_FL  (128 * 4096)           // per-(e,mtile) packed H: 524288 floats

// ---------------------------------------------------------------------------
// Scratch (allocation-free: __device__ globals)
// ---------------------------------------------------------------------------
__device__ int   g_counts[E];
__device__ int   g_pairs[E * T];
__device__ float g_pw[E * T];
__device__ __align__(16) float g_ap[(size_t)E * 32 * ATILE_FL];   // packed gathered x (134 MB)
__device__ __align__(16) float g_hp[(size_t)E * 32 * HTILE_FL];   // packed SwiGLU acts (536 MB)
__device__ __align__(16) float g_w13[(size_t)E * 64 * 32 * 4096]; // packed w1|w3 (268 MB)
__device__ __align__(16) float g_w2p[(size_t)E * 8 * 128 * 4096]; // packed w2 (67 MB)

// ---------------------------------------------------------------------------
// helpers (sm_80+ ISA only)
// ---------------------------------------------------------------------------
__device__ __forceinline__ uint32_t f2tf(float f) {
    uint32_t r;
    asm("cvt.rna.tf32.f32 %0, %1;" : "=r"(r) : "f"(f));
    return r;
}
__device__ __forceinline__ float tfr(float f) { return __uint_as_float(f2tf(f)); }

__device__ __forceinline__ void mma8(float* c, const uint32_t* a, const uint32_t* b) {
    asm volatile(
        "mma.sync.aligned.m16n8k8.row.col.f32.tf32.tf32.f32 "
        "{%0,%1,%2,%3}, {%4,%5,%6,%7}, {%8,%9}, {%0,%1,%2,%3};"
        : "+f"(c[0]), "+f"(c[1]), "+f"(c[2]), "+f"(c[3])
        : "r"(a[0]), "r"(a[1]), "r"(a[2]), "r"(a[3]), "r"(b[0]), "r"(b[1]));
}
__device__ __forceinline__ uint32_t cvta_smem(const void* p) {
    uint32_t a;
    asm("{ .reg .u64 t; cvta.to.shared.u64 t, %1; cvt.u32.u64 %0, t; }"
        : "=r"(a) : "l"(p));
    return a;
}
__device__ __forceinline__ void cp16(uint32_t dst, const void* src, int sz) {
    asm volatile("cp.async.cg.shared.global [%0], [%1], 16, %2;"
                 :: "r"(dst), "l"(src), "r"(sz));
}
#define CP_COMMIT() asm volatile("cp.async.commit_group;" ::: "memory")
#define CP_WAIT1()  asm volatile("cp.async.wait_group 1;" ::: "memory")

// ---------------------------------------------------------------------------
// Zero output + counters
// ---------------------------------------------------------------------------
__global__ void zero_kernel(float* __restrict__ out) {
    int idx = blockIdx.x * blockDim.x + threadIdx.x;
    const int total = T * D;
    for (int i = idx; i < total; i += gridDim.x * blockDim.x) out[i] = 0.0f;
    if (idx < E) g_counts[idx] = 0;
}

// ---------------------------------------------------------------------------
// Prepass: pack w1|w3 into mma-B-fragment order, tf32-rounded.
// Layout: [e][nt(64)][kt(32)][wg(4)][ks(4)][32 slots x 8 floats]
// Slot swizzle: physical uint4 ph at lane*2+ph holds logical j = ph ^ (r&1).
// ---------------------------------------------------------------------------
__global__ void pack_w13(const float* __restrict__ w1, const float* __restrict__ w3) {
    size_t i4 = (size_t)blockIdx.x * blockDim.x + threadIdx.x;
    const size_t tot = (size_t)E * 64 * 32 * 4096 / 4;
    for (; i4 < tot; i4 += (size_t)gridDim.x * blockDim.x) {
        uint32_t p4 = (uint32_t)(i4 & 63);
        uint32_t ks = (uint32_t)((i4 >> 6) & 3);
        uint32_t wg = (uint32_t)((i4 >> 8) & 3);
        uint32_t kt = (uint32_t)((i4 >> 10) & 31);
        uint32_t nt = (uint32_t)((i4 >> 15) & 63);
        uint32_t e  = (uint32_t)(i4 >> 21);
        uint32_t lane = p4 >> 1, ph = p4 & 1;
        uint32_t r = lane >> 2, c = lane & 3;
        uint32_t j = ph ^ (r & 1);
        const float* src = (wg >= 2 ? w3 : w1) + (size_t)e * D * F;
        int colb = nt * 64 + (wg & 1) * 32 + r;
        int kb   = kt * 32 + ks * 8 + c;
        float4 v; float* vp = &v.x;
#pragma unroll
        for (int q = 0; q < 4; q++) {
            int nj = (j << 1) + (q >> 1);
            int k  = kb + (q & 1) * 4;
            vp[q] = tfr(src[(size_t)k * F + colb + nj * 8]);
        }
        ((float4*)g_w13)[i4] = v;
    }
}

// ---------------------------------------------------------------------------
// Prepass: pack w2. Layout: [e][nt(8)][kt(128)][wg(4)][ks(4)][32x8]
// ---------------------------------------------------------------------------
__global__ void pack_w2(const float* __restrict__ w2) {
    size_t i4 = (size_t)blockIdx.x * blockDim.x + threadIdx.x;
    const size_t tot = (size_t)E * 8 * 128 * 4096 / 4;
    for (; i4 < tot; i4 += (size_t)gridDim.x * blockDim.x) {
        uint32_t p4 = (uint32_t)(i4 & 63);
        uint32_t ks = (uint32_t)((i4 >> 6) & 3);
        uint32_t wg = (uint32_t)((i4 >> 8) & 3);
        uint32_t kt = (uint32_t)((i4 >> 10) & 127);
        uint32_t nt = (uint32_t)((i4 >> 17) & 7);
        uint32_t e  = (uint32_t)(i4 >> 20);
        uint32_t lane = p4 >> 1, ph = p4 & 1;
        uint32_t r = lane >> 2, c = lane & 3;
        uint32_t j = ph ^ (r & 1);
        const float* src = w2 + (size_t)e * F * D;
        int colb = nt * 128 + wg * 32 + r;
        int kb   = kt * 32 + ks * 8 + c;
        float4 v; float* vp = &v.x;
#pragma unroll
        for (int q = 0; q < 4; q++) {
            int nj = (j << 1) + (q >> 1);
            int k  = kb + (q & 1) * 4;
            vp[q] = tfr(src[(size_t)k * D + colb + nj * 8]);
        }
        ((float4*)g_w2p)[i4] = v;
    }
}

// ---------------------------------------------------------------------------
// Router (unchanged — known correct)
// ---------------------------------------------------------------------------
__global__ void router_kernel(const float* __restrict__ x,
                              const float* __restrict__ gw,
                              const float* __restrict__ gb) {
    int t   = blockIdx.x;
    int tid = threadIdx.x;
    __shared__ float s[128][E];

    float acc[E];
#pragma unroll
    for (int e = 0; e < E; e++) acc[e] = 0.0f;

    const float* xr = x + (size_t)t * D;
    for (int d = tid; d < D; d += 128) {
        float xv = xr[d];
#pragma unroll
        for (int e = 0; e < E; e++) acc[e] += xv * gw[d * E + e];
    }
#pragma unroll
    for (int e = 0; e < E; e++) s[tid][e] = acc[e];
    __syncthreads();

    if (tid == 0) {
        float l[E];
#pragma unroll
        for (int e = 0; e < E; e++) {
            float a = 0.0f;
            for (int i = 0; i < 128; i++) a += s[i][e];
            l[e] = a + gb[e];
        }
        int i1 = 0;
        for (int e = 1; e < E; e++) if (l[e] > l[i1]) i1 = e;
        int i2 = -1;
        for (int e = 0; e < E; e++) {
            if (e == i1) continue;
            if (i2 < 0 || l[e] > l[i2]) i2 = e;
        }
        float wb  = expf(l[i2] - l[i1]);
        float w1n = 1.0f / (1.0f + wb);
        float w2n = wb * w1n;

        int p0 = atomicAdd(&g_counts[i1], 1);
        g_pairs[i1 * T + p0] = (t << 1);
        g_pw[i1 * T + p0]    = w1n;
        int p1 = atomicAdd(&g_counts[i2], 1);
        g_pairs[i2 * T + p1] = (t << 1) | 1;
        g_pw[i2 * T + p1]    = w2n;
    }
}

// ---------------------------------------------------------------------------
// Prepass: pack gathered A tiles (x rows per expert m-tile) into mma
// A-fragment order, tf32-rounded.
// Layout per (e, mtile): [kt(32)][ks(4)][mf(8)][lane(32)][reg(4)]
// reg j -> element (m = mf*16 + (j&1)*8 + r, k = kt*32 + ks*8 + (j>>1)*4 + c)
// ---------------------------------------------------------------------------
__global__ void pack_a(const float* __restrict__ x) {
    int e  = blockIdx.y;
    int cnt = g_counts[e];
    int m0 = blockIdx.x * 128;
    if (m0 >= cnt) return;
    int tid = threadIdx.x;

    float* dst = g_ap + (size_t)(e * 32 + blockIdx.x) * ATILE_FL;

    // token row pointers for the two rows each lane touches per chunk are
    // resolved per chunk (g_pairs reads hit L1).
    for (int i = 0; i < 128; i++) {
        int cid = tid + i * 256;              // 0..32767
        int lane = cid & 31;
        int mf   = (cid >> 5) & 7;
        int ks   = (cid >> 8) & 3;
        int kt   = cid >> 10;                 // 0..31
        int r = lane >> 2, c = lane & 3;
        int kb = kt * 32 + ks * 8 + c;
        float4 v; float* vp = &v.x;
#pragma unroll
        for (int j = 0; j < 4; j++) {
            int m = mf * 16 + (j & 1) * 8 + r;
            int k = kb + (j >> 1) * 4;
            float val = 0.0f;
            if (m0 + m < cnt) {
                int tok = g_pairs[e * T + m0 + m] >> 1;
                val = tfr(x[(size_t)tok * D + k]);
            }
            vp[j] = val;
        }
        ((float4*)dst)[cid] = v;
    }
}

// ===========================================================================
// GEMM1: CTA tile 128(M) x [64(w1)|64(w3)] stacked N=128. K = D (32 ktiles).
// 256 thr, 8 warps = 2Mx4N, warp 64x32. All operands fragment-packed:
// A frag = 1 LDS.128, B frags = 2 LDS.128 per ks. cp.async 3-stage.
// Epilogue: SwiGLU via smem exchange -> fragment-packed g_hp.
// ===========================================================================
__global__ __launch_bounds__(256, 2)
void gemm1_mma(const float* __restrict__ dummy) {
    int e   = blockIdx.z;
    int cnt = g_counts[e];
    int m0  = blockIdx.x * 128;
    if (m0 >= cnt) return;
    int n0  = blockIdx.y * 64;

    extern __shared__ float sm[];
    uint32_t smb = cvta_smem(sm);
    int tid = threadIdx.x;

    const float* abase = g_ap + (size_t)(e * 32 + blockIdx.x) * ATILE_FL;
    const float* bbase = g_w13 + (size_t)(e * 64 + blockIdx.y) * 32 * 4096;
    int cofs[4];
#pragma unroll
    for (int i = 0; i < 4; i++) cofs[i] = (tid + i * 256) * 4;

    // compute mapping: 8 warps = 2M x 4N(stacked), warp tile 64x32
    int wid = tid >> 5, lane = tid & 31;
    int wmb = (wid >> 2) * 4;            // A mf base (0 or 4)
    int wgq = wid & 3;                   // N warp-group
    int wn = wgq * 32;
    int r = lane >> 2, c = lane & 3;
    int xs = (lane & 4) ? 4 : 0;         // B swizzle offset
    int bwoff = (wgq << 10) + lane * 8;
    int awoff = lane * 4;

    float acc[4][4][4];
#pragma unroll
    for (int mi = 0; mi < 4; mi++)
#pragma unroll
        for (int nj = 0; nj < 4; nj++)
#pragma unroll
            for (int q = 0; q < 4; q++) acc[mi][nj][q] = 0.f;

    const int KT = D / 32;               // 32

#pragma unroll
    for (int st = 0; st < 2; st++) {
        uint32_t sb = smb + st * STAGE_BYTES;
#pragma unroll
        for (int i = 0; i < 4; i++) {
            cp16(sb + cofs[i] * 4,               abase + (size_t)st * 4096 + cofs[i], 16);
            cp16(sb + (A_STAGE + cofs[i]) * 4,   bbase + (size_t)st * 4096 + cofs[i], 16);
        }
        CP_COMMIT();
    }

    int stage = 0;
    for (int kt = 0; kt < KT; kt++) {
        CP_WAIT1();
        __syncthreads();
        if (kt + 2 < KT) {
            int ns = (kt + 2) % NSTAGE;
            uint32_t sb = smb + ns * STAGE_BYTES;
#pragma unroll
            for (int i = 0; i < 4; i++) {
                cp16(sb + cofs[i] * 4,             abase + (size_t)(kt + 2) * 4096 + cofs[i], 16);
                cp16(sb + (A_STAGE + cofs[i]) * 4, bbase + (size_t)(kt + 2) * 4096 + cofs[i], 16);
            }
        }
        CP_COMMIT();

        const float* As = sm + stage * STAGE_FL;
        const float* Bs = As + A_STAGE;
#pragma unroll
        for (int ks = 0; ks < 4; ks++) {
            uint4 af[4];
#pragma unroll
            for (int mi = 0; mi < 4; mi++)
                af[mi] = *(const uint4*)(As + ((ks * 8 + wmb + mi) << 7) + awoff);
            const float* Bks = Bs + bwoff + (ks << 8);
            uint4 b01 = *(const uint4*)(Bks + xs);
            uint4 b23 = *(const uint4*)(Bks + (xs ^ 4));
#pragma unroll
            for (int mi = 0; mi < 4; mi++) {
                mma8(acc[mi][0], (const uint32_t*)&af[mi], (const uint32_t*)&b01);
                mma8(acc[mi][1], (const uint32_t*)&af[mi], ((const uint32_t*)&b01) + 2);
                mma8(acc[mi][2], (const uint32_t*)&af[mi], (const uint32_t*)&b23);
                mma8(acc[mi][3], (const uint32_t*)&af[mi], ((const uint32_t*)&b23) + 2);
            }
        }
        stage = (stage + 1) % NSTAGE;
    }

    // ---- SwiGLU epilogue: smem exchange, then fragment-packed g_hp ----
    __syncthreads();
    float* hx = sm;                      // [128][132]
#pragma unroll
    for (int mi = 0; mi < 4; mi++)
#pragma unroll
        for (int h = 0; h < 2; h++) {
            int m = (wmb + mi) * 16 + r + h * 8;
#pragma unroll
            for (int nj = 0; nj < 4; nj++) {
                int col = wn + nj * 8 + c * 2;
                *(float2*)&hx[m * 132 + col] =
                    make_float2(acc[mi][nj][h * 2], acc[mi][nj][h * 2 + 1]);
            }
        }
    __syncthreads();
    float* hdst = g_hp + (size_t)(e * 32 + blockIdx.x) * HTILE_FL
                + (size_t)(n0 >> 5) * 4096;
#pragma unroll
    for (int i = 0; i < 8; i++) {
        int cid = tid + i * 256;         // [ktl(2)][ks(4)][mf(8)][lane(32)]
        int lane2 = cid & 31;
        int mf   = (cid >> 5) & 7;
        int ks   = (cid >> 8) & 3;
        int ktl  = cid >> 10;            // 0..1
        int r2 = lane2 >> 2, c2 = lane2 & 3;
        float4 o; float* op = &o.x;
#pragma unroll
        for (int j = 0; j < 4; j++) {
            int m = mf * 16 + (j & 1) * 8 + r2;
            int kc = ktl * 32 + ks * 8 + (j >> 1) * 4 + c2;
            float v1 = hx[m * 132 + kc];
            float v3 = hx[m * 132 + 64 + kc];
            op[j] = tfr(v1 / (1.0f + __expf(-v1)) * v3);
        }
        *(float4*)(hdst + (size_t)ktl * 4096 + ((ks * 8 + mf) * 32 + lane2) * 4) = o;
    }
}

// ===========================================================================
// GEMM2: CTA tile 128(M) x 128(D). K = F (128 ktiles). Fragment-packed A
// (g_hp) and B (g_w2p); linear staging. Weighted atomicAdd combine.
// ===========================================================================
__global__ __launch_bounds__(256, 2)
void gemm2_mma(float* __restrict__ out) {
    int e   = blockIdx.z;
    int cnt = g_counts[e];
    int m0  = blockIdx.x * 128;
    if (m0 >= cnt) return;
    int n0  = blockIdx.y * 128;

    extern __shared__ float sm[];
    uint32_t smb = cvta_smem(sm);
    int tid = threadIdx.x;

    const float* abase = g_hp + (size_t)(e * 32 + blockIdx.x) * HTILE_FL;
    const float* bbase = g_w2p + (size_t)(e * 8 + blockIdx.y) * 128 * 4096;
    int cofs[4];
#pragma unroll
    for (int i = 0; i < 4; i++) cofs[i] = (tid + i * 256) * 4;

    int wid = tid >> 5, lane = tid & 31;
    int wmb = (wid >> 2) * 4;
    int wgq = wid & 3;
    int wn = wgq * 32;
    int r = lane >> 2, c = lane & 3;
    int xs = (lane & 4) ? 4 : 0;
    int bwoff = (wgq << 10) + lane * 8;
    int awoff = lane * 4;

    float acc[4][4][4];
#pragma unroll
    for (int mi = 0; mi < 4; mi++)
#pragma unroll
        for (int nj = 0; nj < 4; nj++)
#pragma unroll
            for (int q = 0; q < 4; q++) acc[mi][nj][q] = 0.f;

    const int KT = F / 32;               // 128

#pragma unroll
    for (int st = 0; st < 2; st++) {
        uint32_t sb = smb + st * STAGE_BYTES;
#pragma unroll
        for (int i = 0; i < 4; i++) {
            cp16(sb + cofs[i] * 4,             abase + (size_t)st * 4096 + cofs[i], 16);
            cp16(sb + (A_STAGE + cofs[i]) * 4, bbase + (size_t)st * 4096 + cofs[i], 16);
        }
        CP_COMMIT();
    }

    int stage = 0;
    for (int kt = 0; kt < KT; kt++) {
        CP_WAIT1();
        __syncthreads();
        if (kt + 2 < KT) {
            int ns = (kt + 2) % NSTAGE;
            uint32_t sb = smb + ns * STAGE_BYTES;
#pragma unroll
            for (int i = 0; i < 4; i++) {
                cp16(sb + cofs[i] * 4,             abase + (size_t)(kt + 2) * 4096 + cofs[i], 16);
                cp16(sb + (A_STAGE + cofs[i]) * 4, bbase + (size_t)(kt + 2) * 4096 + cofs[i], 16);
            }
        }
        CP_COMMIT();

        const float* As = sm + stage * STAGE_FL;
        const float* Bs = As + A_STAGE;
#pragma unroll
        for (int ks = 0; ks < 4; ks++) {
            uint4 af[4];
#pragma unroll
            for (int mi = 0; mi < 4; mi++)
                af[mi] = *(const uint4*)(As + ((ks * 8 + wmb + mi) << 7) + awoff);
            const float* Bks = Bs + bwoff + (ks << 8);
            uint4 b01 = *(const uint4*)(Bks + xs);
            uint4 b23 = *(const uint4*)(Bks + (xs ^ 4));
#pragma unroll
            for (int mi = 0; mi < 4; mi++) {
                mma8(acc[mi][0], (const uint32_t*)&af[mi], (const uint32_t*)&b01);
                mma8(acc[mi][1], (const uint32_t*)&af[mi], ((const uint32_t*)&b01) + 2);
                mma8(acc[mi][2], (const uint32_t*)&af[mi], (const uint32_t*)&b23);
                mma8(acc[mi][3], (const uint32_t*)&af[mi], ((const uint32_t*)&b23) + 2);
            }
        }
        stage = (stage + 1) % NSTAGE;
    }

    // weighted combine (atomicAdd: commutative -> deterministic)
#pragma unroll
    for (int mi = 0; mi < 4; mi++)
#pragma unroll
        for (int h = 0; h < 2; h++) {
            int m = m0 + (wmb + mi) * 16 + r + h * 8;
            if (m >= cnt) continue;
            int pair = g_pairs[e * T + m];
            float w  = g_pw[e * T + m];
            float* orow = out + (size_t)(pair >> 1) * D + n0;
#pragma unroll
            for (int nj = 0; nj < 4; nj++) {
                int col = wn + nj * 8 + c * 2;
                atomicAdd(orow + col,     w * acc[mi][nj][h * 2]);
                atomicAdd(orow + col + 1, w * acc[mi][nj][h * 2 + 1]);
            }
        }
}

// ---------------------------------------------------------------------------
extern "C" void kernel_launch(void* const* d_in, const int* in_sizes, int n_in,
                              void* d_out, int out_size) {
    const float* x  = (const float*)d_in[0];   // [T, D]
    const float* gw = (const float*)d_in[1];   // [D, E]
    const float* gb = (const float*)d_in[2];   // [E]
    const float* w1 = (const float*)d_in[3];   // [E, D, F]
    const float* w3 = (const float*)d_in[4];   // [E, D, F]
    const float* w2 = (const float*)d_in[5];   // [E, F, D]
    float* out = (float*)d_out;                // [T, D]

    (void)cudaFuncSetAttribute(gemm1_mma, cudaFuncAttributeMaxDynamicSharedMemorySize, G_SMEM);
    (void)cudaFuncSetAttribute(gemm2_mma, cudaFuncAttributeMaxDynamicSharedMemorySize, G_SMEM);

    zero_kernel<<<2048, 256>>>(out);
    pack_w13<<<8192, 256>>>(w1, w3);
    pack_w2<<<8192, 256>>>(w2);
    router_kernel<<<T, 128>>>(x, gw, gb);
    pack_a<<<dim3(T / 128, E), 256>>>(x);
    gemm1_mma<<<dim3(T / 128, F / 64, E), 256, G_SMEM>>>(nullptr);
    gemm2_mma<<<dim3(T / 128, D / 128, E), 256, G_SMEM>>>(out);
}

// round 17
// speedup vs baseline: 4.1100x; 1.0460x over previous
#include <cuda_runtime.h>
#include <math.h>
#include <stdint.h>

// Problem dims (fixed by reference)
#define T   4096      // tokens = B*S
#define D   1024      // hidden
#define F   4096      // ffn
#define E   8         // experts

// Tiling
#define A_STAGE 4096                     // packed A tile (128m x 32k), linear
#define B_STAGE 4096                     // packed B tile (32k x 128n), linear
#define STAGE_FL (A_STAGE + B_STAGE)     // 8192 floats
#define STAGE_BYTES (STAGE_FL * 4)       // 32768
#define NSTAGE 3
#define G_SMEM (NSTAGE * STAGE_BYTES)    // 98304 B

#define ATILE_FL  (32 * 4096)            // per-(e,mtile) packed A: 131072 floats
#define HTILE_FL  (128 * 4096)           // per-(e,mtile) packed H: 524288 floats

// ---------------------------------------------------------------------------
// Scratch (allocation-free: __device__ globals)
// ---------------------------------------------------------------------------
__device__ int   g_counts[E];
__device__ int   g_pairs[E * T];
__device__ float g_pw[E * T];
__device__ __align__(16) float g_ap[(size_t)E * 32 * ATILE_FL];   // packed gathered x
__device__ __align__(16) float g_hp[(size_t)E * 32 * HTILE_FL];   // packed SwiGLU acts
__device__ __align__(16) float g_w13[(size_t)E * 64 * 32 * 4096]; // packed w1|w3
__device__ __align__(16) float g_w2p[(size_t)E * 8 * 128 * 4096]; // packed w2

// ---------------------------------------------------------------------------
// helpers (sm_80+ ISA only)
// ---------------------------------------------------------------------------
__device__ __forceinline__ uint32_t f2tf(float f) {
    uint32_t r;
    asm("cvt.rna.tf32.f32 %0, %1;" : "=r"(r) : "f"(f));
    return r;
}
__device__ __forceinline__ float tfr(float f) { return __uint_as_float(f2tf(f)); }

__device__ __forceinline__ void mma8(float* c, const uint32_t* a, const uint32_t* b) {
    asm volatile(
        "mma.sync.aligned.m16n8k8.row.col.f32.tf32.tf32.f32 "
        "{%0,%1,%2,%3}, {%4,%5,%6,%7}, {%8,%9}, {%0,%1,%2,%3};"
        : "+f"(c[0]), "+f"(c[1]), "+f"(c[2]), "+f"(c[3])
        : "r"(a[0]), "r"(a[1]), "r"(a[2]), "r"(a[3]), "r"(b[0]), "r"(b[1]));
}
__device__ __forceinline__ uint32_t cvta_smem(const void* p) {
    uint32_t a;
    asm("{ .reg .u64 t; cvta.to.shared.u64 t, %1; cvt.u32.u64 %0, t; }"
        : "=r"(a) : "l"(p));
    return a;
}
__device__ __forceinline__ void cp16(uint32_t dst, const void* src, int sz) {
    asm volatile("cp.async.cg.shared.global [%0], [%1], 16, %2;"
                 :: "r"(dst), "l"(src), "r"(sz));
}
#define CP_COMMIT() asm volatile("cp.async.commit_group;" ::: "memory")
#define CP_WAIT1()  asm volatile("cp.async.wait_group 1;" ::: "memory")

// ---------------------------------------------------------------------------
// Zero output + counters
// ---------------------------------------------------------------------------
__global__ void zero_kernel(float* __restrict__ out) {
    int idx = blockIdx.x * blockDim.x + threadIdx.x;
    const int total = T * D;
    for (int i = idx; i < total; i += gridDim.x * blockDim.x) out[i] = 0.0f;
    if (idx < E) g_counts[idx] = 0;
}

// ---------------------------------------------------------------------------
// Prepass: pack w1|w3 (tiled transpose through smem, coalesced reads).
// Output layout per (e,nt,kt): [wg(4)][ks(4)][lane(32)][ph(2)] uint4,
// logical j = ph ^ (r&1); element q -> (n = (wg&1)*32 + r + nj*8 with
// nj = (j<<1)+(q>>1), k = ks*8 + c + (q&1)*4); wg>=2 -> w3.
// ---------------------------------------------------------------------------
__global__ void pack_w13_t(const float* __restrict__ w1, const float* __restrict__ w3) {
    int nt = blockIdx.x, kt = blockIdx.y, e = blockIdx.z;
    int tid = threadIdx.x;
    __shared__ float sw[2][32][65];

    const float* b1 = w1 + (size_t)e * D * F + (size_t)(kt * 32) * F + nt * 64;
    const float* b3 = w3 + (size_t)e * D * F + (size_t)(kt * 32) * F + nt * 64;
#pragma unroll
    for (int i = 0; i < 4; i++) {
        int idx = tid + i * 256;             // 0..1023
        int mat = idx >> 9, rem = idx & 511;
        int k = rem >> 4, n4 = rem & 15;
        float4 v = *(const float4*)((mat ? b3 : b1) + (size_t)k * F + n4 * 4);
        sw[mat][k][n4 * 4 + 0] = v.x;
        sw[mat][k][n4 * 4 + 1] = v.y;
        sw[mat][k][n4 * 4 + 2] = v.z;
        sw[mat][k][n4 * 4 + 3] = v.w;
    }
    __syncthreads();

    float* dst = g_w13 + (size_t)((e * 64 + nt) * 32 + kt) * 4096;
#pragma unroll
    for (int i = 0; i < 4; i++) {
        int o = tid + i * 256;               // uint4 index 0..1023
        int ph = o & 1, lane = (o >> 1) & 31, ks = (o >> 6) & 3, wg = o >> 8;
        int r = lane >> 2, c = lane & 3;
        int j = ph ^ (r & 1);
        int mat = wg >> 1;
        int colb = (wg & 1) * 32 + r;
        float4 v; float* vp = &v.x;
#pragma unroll
        for (int q = 0; q < 4; q++) {
            int nj = (j << 1) + (q >> 1);
            int k  = ks * 8 + c + (q & 1) * 4;
            vp[q] = tfr(sw[mat][k][colb + nj * 8]);
        }
        *(float4*)(dst + o * 4) = v;
    }
}

// ---------------------------------------------------------------------------
// Prepass: pack w2 (tiled transpose). Output per (e,nt,kt): same fragment
// scheme, colb = wg*32 + r over the 128-wide n block.
// ---------------------------------------------------------------------------
__global__ void pack_w2_t(const float* __restrict__ w2) {
    int nt = blockIdx.x, kt = blockIdx.y, e = blockIdx.z;
    int tid = threadIdx.x;
    __shared__ float sw[32][129];

    const float* b = w2 + (size_t)e * F * D + (size_t)(kt * 32) * D + nt * 128;
#pragma unroll
    for (int i = 0; i < 4; i++) {
        int idx = tid + i * 256;             // 0..1023
        int k = idx >> 5, n4 = idx & 31;
        float4 v = *(const float4*)(b + (size_t)k * D + n4 * 4);
        sw[k][n4 * 4 + 0] = v.x;
        sw[k][n4 * 4 + 1] = v.y;
        sw[k][n4 * 4 + 2] = v.z;
        sw[k][n4 * 4 + 3] = v.w;
    }
    __syncthreads();

    float* dst = g_w2p + (size_t)((e * 8 + nt) * 128 + kt) * 4096;
#pragma unroll
    for (int i = 0; i < 4; i++) {
        int o = tid + i * 256;
        int ph = o & 1, lane = (o >> 1) & 31, ks = (o >> 6) & 3, wg = o >> 8;
        int r = lane >> 2, c = lane & 3;
        int j = ph ^ (r & 1);
        int colb = wg * 32 + r;
        float4 v; float* vp = &v.x;
#pragma unroll
        for (int q = 0; q < 4; q++) {
            int nj = (j << 1) + (q >> 1);
            int k  = ks * 8 + c + (q & 1) * 4;
            vp[q] = tfr(sw[k][colb + nj * 8]);
        }
        *(float4*)(dst + o * 4) = v;
    }
}

// ---------------------------------------------------------------------------
// Router: partial sums as before; per-expert reduction parallelized over 8
// threads IN THE SAME i-ascending order (bit-identical logits to prior rev).
// ---------------------------------------------------------------------------
__global__ void router_kernel(const float* __restrict__ x,
                              const float* __restrict__ gw,
                              const float* __restrict__ gb) {
    int t   = blockIdx.x;
    int tid = threadIdx.x;
    __shared__ float s[128][E];
    __shared__ float l[E];

    float acc[E];
#pragma unroll
    for (int e = 0; e < E; e++) acc[e] = 0.0f;

    const float* xr = x + (size_t)t * D;
    for (int d = tid; d < D; d += 128) {
        float xv = xr[d];
#pragma unroll
        for (int e = 0; e < E; e++) acc[e] += xv * gw[d * E + e];
    }
#pragma unroll
    for (int e = 0; e < E; e++) s[tid][e] = acc[e];
    __syncthreads();

    if (tid < E) {
        float a = 0.0f;
        for (int i = 0; i < 128; i++) a += s[i][tid];
        l[tid] = a + gb[tid];
    }
    __syncthreads();

    if (tid == 0) {
        int i1 = 0;
        for (int e = 1; e < E; e++) if (l[e] > l[i1]) i1 = e;
        int i2 = -1;
        for (int e = 0; e < E; e++) {
            if (e == i1) continue;
            if (i2 < 0 || l[e] > l[i2]) i2 = e;
        }
        float wb  = expf(l[i2] - l[i1]);
        float w1n = 1.0f / (1.0f + wb);
        float w2n = wb * w1n;

        int p0 = atomicAdd(&g_counts[i1], 1);
        g_pairs[i1 * T + p0] = (t << 1);
        g_pw[i1 * T + p0]    = w1n;
        int p1 = atomicAdd(&g_counts[i2], 1);
        g_pairs[i2 * T + p1] = (t << 1) | 1;
        g_pw[i2 * T + p1]    = w2n;
    }
}

// ---------------------------------------------------------------------------
// Prepass: pack gathered A tiles (tiled: coalesced row reads -> smem ->
// fragment writes). Per (e,mt,kt): out[ks(4)][mf(8)][lane(32)] uint4,
// reg j -> (m = mf*16 + (j&1)*8 + r, k = ks*8 + (j>>1)*4 + c).
// ---------------------------------------------------------------------------
__global__ void pack_a_t(const float* __restrict__ x) {
    int mt = blockIdx.x, kt = blockIdx.y, e = blockIdx.z;
    int cnt = g_counts[e];
    int m0 = mt * 128;
    if (m0 >= cnt) return;
    int tid = threadIdx.x;
    __shared__ float sa[128][33];

#pragma unroll
    for (int i = 0; i < 4; i++) {
        int idx = tid + i * 256;             // 0..1023
        int m = idx >> 3, k4 = idx & 7;
        float4 v = make_float4(0.f, 0.f, 0.f, 0.f);
        if (m0 + m < cnt) {
            int tok = g_pairs[e * T + m0 + m] >> 1;
            v = *(const float4*)(x + (size_t)tok * D + kt * 32 + k4 * 4);
        }
        sa[m][k4 * 4 + 0] = v.x;
        sa[m][k4 * 4 + 1] = v.y;
        sa[m][k4 * 4 + 2] = v.z;
        sa[m][k4 * 4 + 3] = v.w;
    }
    __syncthreads();

    float* dst = g_ap + (size_t)(e * 32 + mt) * ATILE_FL + (size_t)kt * 4096;
#pragma unroll
    for (int i = 0; i < 4; i++) {
        int o = tid + i * 256;               // uint4 index 0..1023
        int lane = o & 31, mf = (o >> 5) & 7, ks = o >> 8;
        int r = lane >> 2, c = lane & 3;
        float4 v; float* vp = &v.x;
#pragma unroll
        for (int j = 0; j < 4; j++) {
            int m = mf * 16 + (j & 1) * 8 + r;
            int k = ks * 8 + (j >> 1) * 4 + c;
            vp[j] = tfr(sa[m][k]);
        }
        *(float4*)(dst + o * 4) = v;
    }
}

// ===========================================================================
// GEMM1: CTA tile 128(M) x [64(w1)|64(w3)] stacked N=128. K = D (32 ktiles).
// 256 thr, 8 warps = 2Mx4N, warp 64x32. All operands fragment-packed.
// (unchanged from prior passing rev)
// ===========================================================================
__global__ __launch_bounds__(256, 2)
void gemm1_mma(const float* __restrict__ dummy) {
    int e   = blockIdx.z;
    int cnt = g_counts[e];
    int m0  = blockIdx.x * 128;
    if (m0 >= cnt) return;
    int n0  = blockIdx.y * 64;

    extern __shared__ float sm[];
    uint32_t smb = cvta_smem(sm);
    int tid = threadIdx.x;

    const float* abase = g_ap + (size_t)(e * 32 + blockIdx.x) * ATILE_FL;
    const float* bbase = g_w13 + (size_t)(e * 64 + blockIdx.y) * 32 * 4096;
    int cofs[4];
#pragma unroll
    for (int i = 0; i < 4; i++) cofs[i] = (tid + i * 256) * 4;

    int wid = tid >> 5, lane = tid & 31;
    int wmb = (wid >> 2) * 4;
    int wgq = wid & 3;
    int wn = wgq * 32;
    int r = lane >> 2, c = lane & 3;
    int xs = (lane & 4) ? 4 : 0;
    int bwoff = (wgq << 10) + lane * 8;
    int awoff = lane * 4;

    float acc[4][4][4];
#pragma unroll
    for (int mi = 0; mi < 4; mi++)
#pragma unroll
        for (int nj = 0; nj < 4; nj++)
#pragma unroll
            for (int q = 0; q < 4; q++) acc[mi][nj][q] = 0.f;

    const int KT = D / 32;

#pragma unroll
    for (int st = 0; st < 2; st++) {
        uint32_t sb = smb + st * STAGE_BYTES;
#pragma unroll
        for (int i = 0; i < 4; i++) {
            cp16(sb + cofs[i] * 4,             abase + (size_t)st * 4096 + cofs[i], 16);
            cp16(sb + (A_STAGE + cofs[i]) * 4, bbase + (size_t)st * 4096 + cofs[i], 16);
        }
        CP_COMMIT();
    }

    int stage = 0;
    for (int kt = 0; kt < KT; kt++) {
        CP_WAIT1();
        __syncthreads();
        if (kt + 2 < KT) {
            int ns = (kt + 2) % NSTAGE;
            uint32_t sb = smb + ns * STAGE_BYTES;
#pragma unroll
            for (int i = 0; i < 4; i++) {
                cp16(sb + cofs[i] * 4,             abase + (size_t)(kt + 2) * 4096 + cofs[i], 16);
                cp16(sb + (A_STAGE + cofs[i]) * 4, bbase + (size_t)(kt + 2) * 4096 + cofs[i], 16);
            }
        }
        CP_COMMIT();

        const float* As = sm + stage * STAGE_FL;
        const float* Bs = As + A_STAGE;
#pragma unroll
        for (int ks = 0; ks < 4; ks++) {
            uint4 af[4];
#pragma unroll
            for (int mi = 0; mi < 4; mi++)
                af[mi] = *(const uint4*)(As + ((ks * 8 + wmb + mi) << 7) + awoff);
            const float* Bks = Bs + bwoff + (ks << 8);
            uint4 b01 = *(const uint4*)(Bks + xs);
            uint4 b23 = *(const uint4*)(Bks + (xs ^ 4));
#pragma unroll
            for (int mi = 0; mi < 4; mi++) {
                mma8(acc[mi][0], (const uint32_t*)&af[mi], (const uint32_t*)&b01);
                mma8(acc[mi][1], (const uint32_t*)&af[mi], ((const uint32_t*)&b01) + 2);
                mma8(acc[mi][2], (const uint32_t*)&af[mi], (const uint32_t*)&b23);
                mma8(acc[mi][3], (const uint32_t*)&af[mi], ((const uint32_t*)&b23) + 2);
            }
        }
        stage = (stage + 1) % NSTAGE;
    }

    // ---- SwiGLU epilogue: smem exchange, then fragment-packed g_hp ----
    __syncthreads();
    float* hx = sm;
#pragma unroll
    for (int mi = 0; mi < 4; mi++)
#pragma unroll
        for (int h = 0; h < 2; h++) {
            int m = (wmb + mi) * 16 + r + h * 8;
#pragma unroll
            for (int nj = 0; nj < 4; nj++) {
                int col = wn + nj * 8 + c * 2;
                *(float2*)&hx[m * 132 + col] =
                    make_float2(acc[mi][nj][h * 2], acc[mi][nj][h * 2 + 1]);
            }
        }
    __syncthreads();
    float* hdst = g_hp + (size_t)(e * 32 + blockIdx.x) * HTILE_FL
                + (size_t)(n0 >> 5) * 4096;
#pragma unroll
    for (int i = 0; i < 8; i++) {
        int cid = tid + i * 256;
        int lane2 = cid & 31;
        int mf   = (cid >> 5) & 7;
        int ks   = (cid >> 8) & 3;
        int ktl  = cid >> 10;
        int r2 = lane2 >> 2, c2 = lane2 & 3;
        float4 o; float* op = &o.x;
#pragma unroll
        for (int j = 0; j < 4; j++) {
            int m = mf * 16 + (j & 1) * 8 + r2;
            int kc = ktl * 32 + ks * 8 + (j >> 1) * 4 + c2;
            float v1 = hx[m * 132 + kc];
            float v3 = hx[m * 132 + 64 + kc];
            op[j] = tfr(v1 / (1.0f + __expf(-v1)) * v3);
        }
        *(float4*)(hdst + (size_t)ktl * 4096 + ((ks * 8 + mf) * 32 + lane2) * 4) = o;
    }
}

// ===========================================================================
// GEMM2: CTA tile 128(M) x 128(D). K = F (128 ktiles). Fragment-packed A/B.
// (unchanged from prior passing rev)
// ===========================================================================
__global__ __launch_bounds__(256, 2)
void gemm2_mma(float* __restrict__ out) {
    int e   = blockIdx.z;
    int cnt = g_counts[e];
    int m0  = blockIdx.x * 128;
    if (m0 >= cnt) return;
    int n0  = blockIdx.y * 128;

    extern __shared__ float sm[];
    uint32_t smb = cvta_smem(sm);
    int tid = threadIdx.x;

    const float* abase = g_hp + (size_t)(e * 32 + blockIdx.x) * HTILE_FL;
    const float* bbase = g_w2p + (size_t)(e * 8 + blockIdx.y) * 128 * 4096;
    int cofs[4];
#pragma unroll
    for (int i = 0; i < 4; i++) cofs[i] = (tid + i * 256) * 4;

    int wid = tid >> 5, lane = tid & 31;
    int wmb = (wid >> 2) * 4;
    int wgq = wid & 3;
    int wn = wgq * 32;
    int r = lane >> 2, c = lane & 3;
    int xs = (lane & 4) ? 4 : 0;
    int bwoff = (wgq << 10) + lane * 8;
    int awoff = lane * 4;

    float acc[4][4][4];
#pragma unroll
    for (int mi = 0; mi < 4; mi++)
#pragma unroll
        for (int nj = 0; nj < 4; nj++)
#pragma unroll
            for (int q = 0; q < 4; q++) acc[mi][nj][q] = 0.f;

    const int KT = F / 32;

#pragma unroll
    for (int st = 0; st < 2; st++) {
        uint32_t sb = smb + st * STAGE_BYTES;
#pragma unroll
        for (int i = 0; i < 4; i++) {
            cp16(sb + cofs[i] * 4,             abase + (size_t)st * 4096 + cofs[i], 16);
            cp16(sb + (A_STAGE + cofs[i]) * 4, bbase + (size_t)st * 4096 + cofs[i], 16);
        }
        CP_COMMIT();
    }

    int stage = 0;
    for (int kt = 0; kt < KT; kt++) {
        CP_WAIT1();
        __syncthreads();
        if (kt + 2 < KT) {
            int ns = (kt + 2) % NSTAGE;
            uint32_t sb = smb + ns * STAGE_BYTES;
#pragma unroll
            for (int i = 0; i < 4; i++) {
                cp16(sb + cofs[i] * 4,             abase + (size_t)(kt + 2) * 4096 + cofs[i], 16);
                cp16(sb + (A_STAGE + cofs[i]) * 4, bbase + (size_t)(kt + 2) * 4096 + cofs[i], 16);
            }
        }
        CP_COMMIT();

        const float* As = sm + stage * STAGE_FL;
        const float* Bs = As + A_STAGE;
#pragma unroll
        for (int ks = 0; ks < 4; ks++) {
            uint4 af[4];
#pragma unroll
            for (int mi = 0; mi < 4; mi++)
                af[mi] = *(const uint4*)(As + ((ks * 8 + wmb + mi) << 7) + awoff);
            const float* Bks = Bs + bwoff + (ks << 8);
            uint4 b01 = *(const uint4*)(Bks + xs);
            uint4 b23 = *(const uint4*)(Bks + (xs ^ 4));
#pragma unroll
            for (int mi = 0; mi < 4; mi++) {
                mma8(acc[mi][0], (const uint32_t*)&af[mi], (const uint32_t*)&b01);
                mma8(acc[mi][1], (const uint32_t*)&af[mi], ((const uint32_t*)&b01) + 2);
                mma8(acc[mi][2], (const uint32_t*)&af[mi], (const uint32_t*)&b23);
                mma8(acc[mi][3], (const uint32_t*)&af[mi], ((const uint32_t*)&b23) + 2);
            }
        }
        stage = (stage + 1) % NSTAGE;
    }

    // weighted combine (atomicAdd: commutative -> deterministic)
#pragma unroll
    for (int mi = 0; mi < 4; mi++)
#pragma unroll
        for (int h = 0; h < 2; h++) {
            int m = m0 + (wmb + mi) * 16 + r + h * 8;
            if (m >= cnt) continue;
            int pair = g_pairs[e * T + m];
            float w  = g_pw[e * T + m];
            float* orow = out + (size_t)(pair >> 1) * D + n0;
#pragma unroll
            for (int nj = 0; nj < 4; nj++) {
                int col = wn + nj * 8 + c * 2;
                atomicAdd(orow + col,     w * acc[mi][nj][h * 2]);
                atomicAdd(orow + col + 1, w * acc[mi][nj][h * 2 + 1]);
            }
        }
}

// ---------------------------------------------------------------------------
extern "C" void kernel_launch(void* const* d_in, const int* in_sizes, int n_in,
                              void* d_out, int out_size) {
    const float* x  = (const float*)d_in[0];   // [T, D]
    const float* gw = (const float*)d_in[1];   // [D, E]
    const float* gb = (const float*)d_in[2];   // [E]
    const float* w1 = (const float*)d_in[3];   // [E, D, F]
    const float* w3 = (const float*)d_in[4];   // [E, D, F]
    const float* w2 = (const float*)d_in[5];   // [E, F, D]
    float* out = (float*)d_out;                // [T, D]

    (void)cudaFuncSetAttribute(gemm1_mma, cudaFuncAttributeMaxDynamicSharedMemorySize, G_SMEM);
    (void)cudaFuncSetAttribute(gemm2_mma, cudaFuncAttributeMaxDynamicSharedMemorySize, G_SMEM);

    zero_kernel<<<2048, 256>>>(out);
    pack_w13_t<<<dim3(64, 32, E), 256>>>(w1, w3);
    pack_w2_t<<<dim3(8, 128, E), 256>>>(w2);
    router_kernel<<<T, 128>>>(x, gw, gb);
    pack_a_t<<<dim3(32, 32, E), 256>>>(x);
    gemm1_mma<<<dim3(T / 128, F / 64, E), 256, G_SMEM>>>(nullptr);
    gemm2_mma<<<dim3(T / 128, D / 128, E), 256, G_SMEM>>>(out);
}